// round 2
// baseline (speedup 1.0000x reference)
#include <cuda_runtime.h>
#include <cuda_bf16.h>
#include <math.h>

// ---------------- problem constants ----------------
#define BB_ 4
#define TT_ 16
#define PP_ 256
#define EE_ 768
#define HH_ 12
#define DD_ 64
#define DFF_ 3072
#define NN_ (BB_*TT_*PP_)          // 16384 tokens
#define SCALE_ 0.125f              // D^-0.5
#define EPS_ 1e-5f

// ---------------- scratch (static device arrays; no allocation) ----------------
__device__ float g_x [NN_*EE_];
__device__ float g_q [NN_*EE_];
__device__ float g_k [NN_*EE_];
__device__ float g_v [NN_*EE_];
__device__ float g_t [NN_*EE_];
__device__ float g_ff[(size_t)NN_*DFF_];

// ---------------- GEMM: C[M,Nc] = A[M,K] @ W[K,Nc] + bias (opt GELU) ----------------
// 128x128 tile, BK=8, 256 threads, 8x8 microtile (split 4+4 for conflict-free LDS.128)
#define BM 128
#define BN 128
#define BK 8

__device__ __forceinline__ float gelu_exact(float x) {
    return 0.5f * x * (1.0f + erff(x * 0.70710678118654752f));
}

template<bool DO_GELU>
__global__ void __launch_bounds__(256) gemm_bias_kernel(
    const float* __restrict__ A, const float* __restrict__ W,
    const float* __restrict__ bias, float* __restrict__ C,
    int M, int K, int Nc)
{
    __shared__ float As[BK][BM];
    __shared__ float Bs[BK][BN];

    const int tid = threadIdx.x;
    const int bm = blockIdx.y * BM;
    const int bn = blockIdx.x * BN;
    const int tx = tid & 15;
    const int ty = tid >> 4;

    // global-load assignments (1 float4 of A + 1 float4 of B per thread per k-step)
    const int arow = tid >> 1;          // 0..127
    const int acol = (tid & 1) * 4;     // 0 or 4
    const int brow = tid >> 5;          // 0..7
    const int bcol = (tid & 31) * 4;    // 0..124

    const float* Aptr = A + (size_t)(bm + arow) * K + acol;
    const float* Bptr = W + (size_t)brow * Nc + bn + bcol;

    float4 aReg = *(const float4*)(Aptr);
    float4 bReg = *(const float4*)(Bptr);

    float acc[8][8];
    #pragma unroll
    for (int i = 0; i < 8; i++)
        #pragma unroll
        for (int j = 0; j < 8; j++) acc[i][j] = 0.f;

    for (int k0 = 0; k0 < K; k0 += BK) {
        // stage to smem (A transposed)
        As[acol+0][arow] = aReg.x;
        As[acol+1][arow] = aReg.y;
        As[acol+2][arow] = aReg.z;
        As[acol+3][arow] = aReg.w;
        *(float4*)&Bs[brow][bcol] = bReg;
        __syncthreads();

        if (k0 + BK < K) {
            aReg = *(const float4*)(Aptr + k0 + BK);
            bReg = *(const float4*)(Bptr + (size_t)(k0 + BK) * Nc);
        }

        #pragma unroll
        for (int kk = 0; kk < BK; kk++) {
            float af[8], bf[8];
            *(float4*)&af[0] = *(const float4*)&As[kk][ty*4];
            *(float4*)&af[4] = *(const float4*)&As[kk][ty*4 + 64];
            *(float4*)&bf[0] = *(const float4*)&Bs[kk][tx*4];
            *(float4*)&bf[4] = *(const float4*)&Bs[kk][tx*4 + 64];
            #pragma unroll
            for (int i = 0; i < 8; i++)
                #pragma unroll
                for (int j = 0; j < 8; j++)
                    acc[i][j] = fmaf(af[i], bf[j], acc[i][j]);
        }
        __syncthreads();
    }

    // epilogue: bias (+GELU), vectorized stores
    #pragma unroll
    for (int i = 0; i < 8; i++) {
        int row = bm + ty*4 + ((i < 4) ? i : (64 + i - 4));
        #pragma unroll
        for (int jh = 0; jh < 2; jh++) {
            int col0 = bn + tx*4 + jh*64;
            float4 v;
            v.x = acc[i][jh*4+0] + bias[col0+0];
            v.y = acc[i][jh*4+1] + bias[col0+1];
            v.z = acc[i][jh*4+2] + bias[col0+2];
            v.w = acc[i][jh*4+3] + bias[col0+3];
            if (DO_GELU) {
                v.x = gelu_exact(v.x); v.y = gelu_exact(v.y);
                v.z = gelu_exact(v.z); v.w = gelu_exact(v.w);
            }
            *(float4*)&C[(size_t)row * Nc + col0] = v;
        }
    }
}

// ---------------- spatial attention: softmax over P within (b,t,h) ----------------
// grid (B*T, H), 256 threads (one query each), K/V tiles staged in 128KB smem
__global__ void __launch_bounds__(256) spatial_attn_kernel(
    const float* __restrict__ Q, const float* __restrict__ K,
    const float* __restrict__ V, float* __restrict__ O)
{
    const int bt = blockIdx.x;
    const int h  = blockIdx.y;
    extern __shared__ float sm[];
    float* Ks = sm;                // [256][64]
    float* Vs = sm + PP_*DD_;      // [256][64]

    const int tid = threadIdx.x;
    const size_t base = (size_t)bt * PP_ * EE_ + h * DD_;

    for (int idx = tid; idx < PP_*DD_; idx += 256) {
        int p = idx >> 6, d = idx & 63;
        size_t g = base + (size_t)p * EE_ + d;
        Ks[idx] = K[g];
        Vs[idx] = V[g];
    }
    __syncthreads();

    // this thread's query row
    float qf[DD_];
    const float* qp = Q + base + (size_t)tid * EE_;
    #pragma unroll
    for (int d4 = 0; d4 < DD_/4; d4++) {
        float4 t = *(const float4*)(qp + d4*4);
        qf[d4*4+0]=t.x; qf[d4*4+1]=t.y; qf[d4*4+2]=t.z; qf[d4*4+3]=t.w;
    }

    float m = -1e30f, l = 0.f;
    float acc[DD_];
    #pragma unroll
    for (int d = 0; d < DD_; d++) acc[d] = 0.f;

    for (int j = 0; j < PP_; j++) {
        const float4* kj = (const float4*)(Ks + j*DD_);
        float s = 0.f;
        #pragma unroll
        for (int d4 = 0; d4 < DD_/4; d4++) {
            float4 kv = kj[d4];
            s = fmaf(qf[d4*4+0], kv.x, s);
            s = fmaf(qf[d4*4+1], kv.y, s);
            s = fmaf(qf[d4*4+2], kv.z, s);
            s = fmaf(qf[d4*4+3], kv.w, s);
        }
        s *= SCALE_;
        float mn = fmaxf(m, s);
        float c  = __expf(m - mn);
        float pj = __expf(s - mn);
        l = l * c + pj;
        const float4* vj = (const float4*)(Vs + j*DD_);
        #pragma unroll
        for (int d4 = 0; d4 < DD_/4; d4++) {
            float4 vv = vj[d4];
            acc[d4*4+0] = fmaf(acc[d4*4+0], c, pj*vv.x);
            acc[d4*4+1] = fmaf(acc[d4*4+1], c, pj*vv.y);
            acc[d4*4+2] = fmaf(acc[d4*4+2], c, pj*vv.z);
            acc[d4*4+3] = fmaf(acc[d4*4+3], c, pj*vv.w);
        }
        m = mn;
    }

    float invl = 1.0f / l;
    float* op = O + base + (size_t)tid * EE_;
    #pragma unroll
    for (int d4 = 0; d4 < DD_/4; d4++) {
        float4 v;
        v.x = acc[d4*4+0]*invl; v.y = acc[d4*4+1]*invl;
        v.z = acc[d4*4+2]*invl; v.w = acc[d4*4+3]*invl;
        *(float4*)(op + d4*4) = v;
    }
}

// ---------------- temporal attention: causal softmax over T within (b,p,h) --------
// grid B*P, 192 threads (h = tid/16, tq = tid%16); K/V staged in 96KB smem
__global__ void __launch_bounds__(192) temporal_attn_kernel(
    const float* __restrict__ Q, const float* __restrict__ K,
    const float* __restrict__ V, float* __restrict__ O)
{
    const int bp = blockIdx.x;
    const int b = bp >> 8;
    const int p = bp & 255;
    extern __shared__ float sm[];
    float* Ks = sm;               // [16][768]
    float* Vs = sm + TT_*EE_;

    const int tid = threadIdx.x;
    for (int idx = tid; idx < TT_*EE_; idx += 192) {
        int t = idx / EE_;
        int e = idx - t*EE_;
        size_t g = ((size_t)(b*TT_ + t) * PP_ + p) * EE_ + e;
        Ks[idx] = K[g];
        Vs[idx] = V[g];
    }
    __syncthreads();

    const int h  = tid >> 4;      // 0..11
    const int tq = tid & 15;      // 0..15

    const size_t qoff = ((size_t)(b*TT_ + tq) * PP_ + p) * EE_ + h * DD_;
    float qf[DD_];
    #pragma unroll
    for (int d4 = 0; d4 < DD_/4; d4++) {
        float4 t4 = *(const float4*)(Q + qoff + d4*4);
        qf[d4*4+0]=t4.x; qf[d4*4+1]=t4.y; qf[d4*4+2]=t4.z; qf[d4*4+3]=t4.w;
    }

    float sc[TT_];
    float m = -1e30f;
    #pragma unroll
    for (int s_ = 0; s_ < TT_; s_++) {
        const float* kr = Ks + s_*EE_ + h*DD_;
        float s = 0.f;
        #pragma unroll
        for (int d = 0; d < DD_; d++) s = fmaf(qf[d], kr[d], s);
        s *= SCALE_;
        if (s_ > tq) s = -1e30f;    // causal mask
        sc[s_] = s;
        m = fmaxf(m, s);
    }
    float l = 0.f;
    #pragma unroll
    for (int s_ = 0; s_ < TT_; s_++) {
        sc[s_] = __expf(sc[s_] - m);
        l += sc[s_];
    }
    float inv = 1.0f / l;

    float acc[DD_];
    #pragma unroll
    for (int d = 0; d < DD_; d++) acc[d] = 0.f;
    #pragma unroll
    for (int s_ = 0; s_ < TT_; s_++) {
        const float* vr = Vs + s_*EE_ + h*DD_;
        float w = sc[s_];
        #pragma unroll
        for (int d = 0; d < DD_; d++) acc[d] = fmaf(w, vr[d], acc[d]);
    }

    #pragma unroll
    for (int d4 = 0; d4 < DD_/4; d4++) {
        float4 v;
        v.x = acc[d4*4+0]*inv; v.y = acc[d4*4+1]*inv;
        v.z = acc[d4*4+2]*inv; v.w = acc[d4*4+3]*inv;
        *(float4*)(O + qoff + d4*4) = v;
    }
}

// ---------------- fused residual add + LayerNorm ----------------
// one block per token row; 256 threads * 3 elems = 768
__global__ void __launch_bounds__(256) add_ln_kernel(
    const float* __restrict__ x, const float* __restrict__ r,
    const float* __restrict__ gamma, const float* __restrict__ beta,
    float* __restrict__ out)
{
    const int row = blockIdx.x;
    const float* xr = x + (size_t)row * EE_;
    const float* rr = r + (size_t)row * EE_;

    float vals[3];
    float s = 0.f, ss = 0.f;
    #pragma unroll
    for (int i = 0; i < 3; i++) {
        int e = threadIdx.x + i*256;
        float v = xr[e] + rr[e];
        vals[i] = v;
        s += v;
        ss = fmaf(v, v, ss);
    }
    // warp reduce
    #pragma unroll
    for (int o = 16; o > 0; o >>= 1) {
        s  += __shfl_down_sync(0xffffffffu, s,  o);
        ss += __shfl_down_sync(0xffffffffu, ss, o);
    }
    __shared__ float reds[8], redss[8];
    int warp = threadIdx.x >> 5, lane = threadIdx.x & 31;
    if (lane == 0) { reds[warp] = s; redss[warp] = ss; }
    __syncthreads();
    float ts = 0.f, tss = 0.f;
    #pragma unroll
    for (int w = 0; w < 8; w++) { ts += reds[w]; tss += redss[w]; }

    const float invE = 1.0f / (float)EE_;
    float mean = ts * invE;
    float var  = tss * invE - mean * mean;
    float inv  = rsqrtf(var + EPS_);

    float* orow = out + (size_t)row * EE_;
    #pragma unroll
    for (int i = 0; i < 3; i++) {
        int e = threadIdx.x + i*256;
        orow[e] = (vals[i] - mean) * inv * gamma[e] + beta[e];
    }
}

// ---------------- copy x -> scratch ----------------
__global__ void copy_kernel(float* __restrict__ dst, const float* __restrict__ src, int n4)
{
    int i = blockIdx.x * blockDim.x + threadIdx.x;
    if (i < n4) ((float4*)dst)[i] = ((const float4*)src)[i];
}

// ---------------- host launcher ----------------
// canonical indices (dict order of setup_inputs)
enum { iX=0, iSQW, iSKW, iSVW, iSOW, iSQB, iSKB, iSVB, iSOB, iSG, iSB,
       iTQW, iTKW, iTVW, iTOW, iTQB, iTKB, iTVB, iTOB, iTG, iTB,
       iW1, iB1, iW2, iB2, iG, iBBb };

extern "C" void kernel_launch(void* const* d_in, const int* in_sizes, int n_in,
                              void* d_out, int out_size)
{
    // Resolve input ordering at runtime:
    //  dict order:      idx2 = sk_w (589824)
    //  signature order: idx2 = sq_b (768)
    static const int map_dict[27] = {0,1,2,3,4,5,6,7,8,9,10,11,12,13,14,15,16,17,18,19,20,21,22,23,24,25,26};
    static const int map_sig [27] = {0,1,3,5,7,2,4,6,8,9,10,11,13,15,17,12,14,16,18,19,20,21,22,23,24,25,26};
    const int* mp = (in_sizes[2] == 768) ? map_sig : map_dict;

    const float* in[27];
    for (int i = 0; i < 27; i++) in[i] = (const float*)d_in[mp[i]];

    float *gx, *gq, *gk, *gv, *gt, *gff;
    cudaGetSymbolAddress((void**)&gx,  g_x);
    cudaGetSymbolAddress((void**)&gq,  g_q);
    cudaGetSymbolAddress((void**)&gk,  g_k);
    cudaGetSymbolAddress((void**)&gv,  g_v);
    cudaGetSymbolAddress((void**)&gt,  g_t);
    cudaGetSymbolAddress((void**)&gff, g_ff);

    const int SPAT_SMEM = 2 * PP_ * DD_ * (int)sizeof(float);   // 128 KB
    const int TEMP_SMEM = 2 * TT_ * EE_ * (int)sizeof(float);   //  96 KB
    cudaFuncSetAttribute(spatial_attn_kernel,  cudaFuncAttributeMaxDynamicSharedMemorySize, SPAT_SMEM);
    cudaFuncSetAttribute(temporal_attn_kernel, cudaFuncAttributeMaxDynamicSharedMemorySize, TEMP_SMEM);

    const dim3 gemmBlk(256);
    const dim3 gE(EE_/BN,  NN_/BM);    // (6,128)  -> 768-wide outputs
    const dim3 gF(DFF_/BN, NN_/BM);    // (24,128) -> FFN hidden

    float* out = (float*)d_out;

    // x -> g_x
    copy_kernel<<<(NN_*EE_/4 + 255)/256, 256>>>(gx, in[iX], NN_*EE_/4);

    // ---- spatial block ----
    gemm_bias_kernel<false><<<gE, gemmBlk>>>(gx, in[iSQW], in[iSQB], gq, NN_, EE_, EE_);
    gemm_bias_kernel<false><<<gE, gemmBlk>>>(gx, in[iSKW], in[iSKB], gk, NN_, EE_, EE_);
    gemm_bias_kernel<false><<<gE, gemmBlk>>>(gx, in[iSVW], in[iSVB], gv, NN_, EE_, EE_);
    spatial_attn_kernel<<<dim3(BB_*TT_, HH_), 256, SPAT_SMEM>>>(gq, gk, gv, gt);
    gemm_bias_kernel<false><<<gE, gemmBlk>>>(gt, in[iSOW], in[iSOB], gq, NN_, EE_, EE_);
    add_ln_kernel<<<NN_, 256>>>(gx, gq, in[iSG], in[iSB], gx);

    // ---- temporal block ----
    gemm_bias_kernel<false><<<gE, gemmBlk>>>(gx, in[iTQW], in[iTQB], gq, NN_, EE_, EE_);
    gemm_bias_kernel<false><<<gE, gemmBlk>>>(gx, in[iTKW], in[iTKB], gk, NN_, EE_, EE_);
    gemm_bias_kernel<false><<<gE, gemmBlk>>>(gx, in[iTVW], in[iTVB], gv, NN_, EE_, EE_);
    temporal_attn_kernel<<<BB_*PP_, 192, TEMP_SMEM>>>(gq, gk, gv, gt);
    gemm_bias_kernel<false><<<gE, gemmBlk>>>(gt, in[iTOW], in[iTOB], gq, NN_, EE_, EE_);
    add_ln_kernel<<<NN_, 256>>>(gx, gq, in[iTG], in[iTB], gx);

    // ---- FFN ----
    gemm_bias_kernel<true ><<<gF, gemmBlk>>>(gx,  in[iW1], in[iB1], gff, NN_, EE_,  DFF_);
    gemm_bias_kernel<false><<<gE, gemmBlk>>>(gff, in[iW2], in[iB2], gq,  NN_, DFF_, EE_);
    add_ln_kernel<<<NN_, 256>>>(gx, gq, in[iG], in[iBBb], out);
}

// round 9
// speedup vs baseline: 1.6106x; 1.6106x over previous
#include <cuda_runtime.h>
#include <cuda_bf16.h>
#include <math.h>
#include <stdint.h>

// ---------------- problem constants ----------------
#define BB_ 4
#define TT_ 16
#define PP_ 256
#define EE_ 768
#define HH_ 12
#define DD_ 64
#define DFF_ 3072
#define NN_ (BB_*TT_*PP_)          // 16384 tokens
#define SCALE_ 0.125f              // D^-0.5
#define EPS_ 1e-5f

// ---------------- helpers (base sm_103-safe PTX only) ----------------
__device__ __forceinline__ uint32_t smem_to_u32(const void* smem_ptr) {
    uint32_t addr;
    asm("{ .reg .u64 tmp; cvta.to.shared.u64 tmp, %1; cvt.u32.u64 %0, tmp; }"
        : "=r"(addr) : "l"(smem_ptr));
    return addr;
}
__device__ __forceinline__ void cpa16(uint32_t dst, const void* src) {
    asm volatile("cp.async.cg.shared.global [%0], [%1], 16;" :: "r"(dst), "l"(src));
}
#define CP_COMMIT() asm volatile("cp.async.commit_group;" ::: "memory")
#define CP_WAIT1()  asm volatile("cp.async.wait_group 1;" ::: "memory")

__device__ __forceinline__ void ldsm4(uint32_t* r, uint32_t addr) {
    asm volatile("ldmatrix.sync.aligned.m8n8.x4.shared.b16 {%0,%1,%2,%3}, [%4];"
        : "=r"(r[0]), "=r"(r[1]), "=r"(r[2]), "=r"(r[3]) : "r"(addr));
}
__device__ __forceinline__ void mma16816(float* d, const uint32_t* a, const uint32_t* b) {
    asm volatile(
        "mma.sync.aligned.m16n8k16.row.col.f32.bf16.bf16.f32 "
        "{%0,%1,%2,%3}, {%4,%5,%6,%7}, {%8,%9}, {%0,%1,%2,%3};"
        : "+f"(d[0]), "+f"(d[1]), "+f"(d[2]), "+f"(d[3])
        : "r"(a[0]), "r"(a[1]), "r"(a[2]), "r"(a[3]), "r"(b[0]), "r"(b[1]));
}

// ---------------- scratch (static device arrays; no allocation) ----------------
__device__ float g_x [NN_*EE_];
__device__ float g_q [NN_*EE_];
__device__ float g_k [NN_*EE_];
__device__ float g_v [NN_*EE_];
__device__ float g_t [NN_*EE_];
__device__ float g_ff[(size_t)NN_*DFF_];
// bf16 split activations (max width DFF)
__device__ __nv_bfloat16 g_ahi[(size_t)NN_*DFF_];
__device__ __nv_bfloat16 g_alo[(size_t)NN_*DFF_];
// bf16 split transposed weights [Nc, K]: 8 x 768x768 + 2 x (768*3072)
#define WSZ_E (EE_*EE_)              // 589824
#define WSZ_F (EE_*DFF_)             // 2359296
#define WTOT  (8*WSZ_E + 2*WSZ_F)    // 9437184
__device__ __nv_bfloat16 g_whi[WTOT];
__device__ __nv_bfloat16 g_wlo[WTOT];

// ---------------- weight prep: transpose + hi/lo split ----------------
// W [K, Nc] fp32 -> Thi/Tlo [Nc, K] bf16
__global__ void __launch_bounds__(256) wprep_kernel(
    const float* __restrict__ W, __nv_bfloat16* __restrict__ Thi,
    __nv_bfloat16* __restrict__ Tlo, int K, int Nc)
{
    __shared__ float tile[32][33];
    const int tx = threadIdx.x & 31;
    const int ty = threadIdx.x >> 5;          // 0..7
    const int n0 = blockIdx.x * 32;
    const int k0 = blockIdx.y * 32;
    #pragma unroll
    for (int j = 0; j < 4; j++)
        tile[ty + 8*j][tx] = W[(size_t)(k0 + ty + 8*j) * Nc + n0 + tx];
    __syncthreads();
    #pragma unroll
    for (int j = 0; j < 4; j++) {
        float v = tile[tx][ty + 8*j];
        __nv_bfloat16 h = __float2bfloat16(v);
        __nv_bfloat16 l = __float2bfloat16(v - __bfloat162float(h));
        size_t o = (size_t)(n0 + ty + 8*j) * K + k0 + tx;
        Thi[o] = h;
        Tlo[o] = l;
    }
}

// ---------------- activation split: fp32 -> hi/lo bf16 ----------------
__global__ void __launch_bounds__(256) split_kernel(
    const float* __restrict__ x, __nv_bfloat16* __restrict__ hi,
    __nv_bfloat16* __restrict__ lo, int n)
{
    int i = blockIdx.x * 256 + threadIdx.x;
    if (i < n) {
        float v = x[i];
        __nv_bfloat16 h = __float2bfloat16(v);
        hi[i] = h;
        lo[i] = __float2bfloat16(v - __bfloat162float(h));
    }
}

// ---------------- mma.sync GEMM: C[M,Nc] = (Ahi+Alo)[M,K] @ (Whi+Wlo)^T + bias ----
// Whi/Wlo are pre-transposed [Nc, K] (K contiguous) = col-major B for m16n8k16;
// with K-contiguous atoms, BOTH A and B use non-trans ldmatrix (lane i -> row i/4,
// k-pair (i%4)*2, which is exactly the mma fragment layout for each operand).
// 128x128 CTA tile, BK=32, 256 threads (8 warps, 2x4), cp.async 3-stage pipeline.
// smem rows padded to 40 bf16 (80 B): 80*r mod 128 covers all 8 distinct 16B slots
// -> conflict-free ldmatrix.
#define AROW_  40
#define AROWB_ (AROW_*2)                // 80 bytes per padded row
#define MATB_  (128*AROWB_)             // 10240 bytes per matrix per stage
#define STG_B  (4*MATB_)                // 40960: Ahi, Alo, Bhi, Blo
#define NSTG_  3
#define GSMEM_TOTAL_ (NSTG_*STG_B)      // 122880

__device__ __forceinline__ float gelu_exact(float x) {
    return 0.5f * x * (1.0f + erff(x * 0.70710678118654752f));
}

template<bool DO_GELU>
__global__ void __launch_bounds__(256) mma_gemm_kernel(
    const __nv_bfloat16* __restrict__ Ahi, const __nv_bfloat16* __restrict__ Alo,
    const __nv_bfloat16* __restrict__ Whi, const __nv_bfloat16* __restrict__ Wlo,
    const float* __restrict__ bias, float* __restrict__ C,
    int K, int Nc)
{
    extern __shared__ __align__(128) char smem[];
    const uint32_t sbase = smem_to_u32(smem);
    const int tid  = threadIdx.x;
    const int lane = tid & 31;
    const int wid  = tid >> 5;
    const int wm   = wid >> 2;          // 0..1
    const int wn   = wid & 3;           // 0..3
    const int bm   = blockIdx.y * 128;
    const int bn   = blockIdx.x * 128;
    const int nchunk = K >> 5;          // K/32

    // cp.async assignment: thread -> one row, two 16B chunks
    const int lrow = tid >> 1;          // 0..127
    const int cbc  = (tid & 1) * 2;     // chunk base 0 or 2
    const __nv_bfloat16* gA0 = Ahi + (size_t)(bm + lrow) * K + cbc * 8;
    const __nv_bfloat16* gA1 = Alo + (size_t)(bm + lrow) * K + cbc * 8;
    const __nv_bfloat16* gB0 = Whi + (size_t)(bn + lrow) * K + cbc * 8;
    const __nv_bfloat16* gB1 = Wlo + (size_t)(bn + lrow) * K + cbc * 8;
    const uint32_t dstb = (uint32_t)lrow * AROWB_ + cbc * 16;

    #define ISSUE_STAGE(s, kc) do { \
        uint32_t st_ = sbase + (s) * STG_B + dstb; \
        cpa16(st_,               gA0 + (kc)); cpa16(st_ + 16,               gA0 + (kc) + 8); \
        cpa16(st_ +   MATB_,     gA1 + (kc)); cpa16(st_ +   MATB_ + 16,     gA1 + (kc) + 8); \
        cpa16(st_ + 2*MATB_,     gB0 + (kc)); cpa16(st_ + 2*MATB_ + 16,     gB0 + (kc) + 8); \
        cpa16(st_ + 3*MATB_,     gB1 + (kc)); cpa16(st_ + 3*MATB_ + 16,     gB1 + (kc) + 8); \
    } while (0)

    ISSUE_STAGE(0, 0);  CP_COMMIT();
    ISSUE_STAGE(1, 32); CP_COMMIT();

    float acc[4][4][4];
    #pragma unroll
    for (int mi = 0; mi < 4; mi++)
        #pragma unroll
        for (int nj = 0; nj < 4; nj++)
            #pragma unroll
            for (int r = 0; r < 4; r++) acc[mi][nj][r] = 0.f;

    // ldmatrix per-lane source rows (non-trans for BOTH operands)
    // A x4 atoms: r0=(m0-7,k0) r1=(m8-15,k0) r2=(m0-7,k8) r3=(m8-15,k8)
    const uint32_t a_row = (uint32_t)(wm*64 + (lane & 15)) * AROWB_;
    const uint32_t a_kh  = (uint32_t)(lane >> 4) * 16;
    // B x4 atoms: r0=(n0-7,k0) r1=(n0-7,k8) r2=(n8-15,k0) r3=(n8-15,k8)
    const uint32_t b_row = (uint32_t)(wn*32 + ((lane >> 4) << 3) + (lane & 7)) * AROWB_;
    const uint32_t b_kh  = (uint32_t)((lane >> 3) & 1) * 16;

    for (int c = 0; c < nchunk; ++c) {
        CP_WAIT1();
        __syncthreads();
        if (c + 2 < nchunk) { ISSUE_STAGE((c + 2) % NSTG_, (c + 2) * 32); }
        CP_COMMIT();   // empty group when nothing issued keeps wait-count math uniform

        const uint32_t st = sbase + (c % NSTG_) * STG_B;
        #pragma unroll
        for (int ks = 0; ks < 2; ks++) {
            uint32_t ah[4][4], al[4][4], bh[4][2], bl[4][2];
            const uint32_t akb = (uint32_t)ks*32 + a_kh;
            const uint32_t bkb = (uint32_t)ks*32 + b_kh;
            #pragma unroll
            for (int mi = 0; mi < 4; mi++) {
                ldsm4(ah[mi], st +           a_row + (uint32_t)mi*16*AROWB_ + akb);
                ldsm4(al[mi], st + MATB_ +   a_row + (uint32_t)mi*16*AROWB_ + akb);
            }
            #pragma unroll
            for (int np = 0; np < 2; np++) {
                uint32_t r4[4];
                ldsm4(r4, st + 2*MATB_ + b_row + (uint32_t)np*16*AROWB_ + bkb);
                bh[np*2][0] = r4[0]; bh[np*2][1] = r4[1];
                bh[np*2+1][0] = r4[2]; bh[np*2+1][1] = r4[3];
                ldsm4(r4, st + 3*MATB_ + b_row + (uint32_t)np*16*AROWB_ + bkb);
                bl[np*2][0] = r4[0]; bl[np*2][1] = r4[1];
                bl[np*2+1][0] = r4[2]; bl[np*2+1][1] = r4[3];
            }
            #pragma unroll
            for (int mi = 0; mi < 4; mi++)
                #pragma unroll
                for (int nj = 0; nj < 4; nj++) {
                    mma16816(acc[mi][nj], ah[mi], bh[nj]);   // hi*hi
                    mma16816(acc[mi][nj], ah[mi], bl[nj]);   // hi*lo
                    mma16816(acc[mi][nj], al[mi], bh[nj]);   // lo*hi
                }
        }
        __syncthreads();
    }

    // epilogue: d0,d1 -> (row, col..col+1); d2,d3 -> (row+8, col..col+1)
    #pragma unroll
    for (int mi = 0; mi < 4; mi++) {
        const int r0 = bm + wm*64 + mi*16 + (lane >> 2);
        #pragma unroll
        for (int nj = 0; nj < 4; nj++) {
            const int cc = bn + wn*32 + nj*8 + (lane & 3)*2;
            float b0 = bias[cc], b1 = bias[cc+1];
            float2 v0, v1;
            v0.x = acc[mi][nj][0] + b0; v0.y = acc[mi][nj][1] + b1;
            v1.x = acc[mi][nj][2] + b0; v1.y = acc[mi][nj][3] + b1;
            if (DO_GELU) {
                v0.x = gelu_exact(v0.x); v0.y = gelu_exact(v0.y);
                v1.x = gelu_exact(v1.x); v1.y = gelu_exact(v1.y);
            }
            *(float2*)&C[(size_t)r0      * Nc + cc] = v0;
            *(float2*)&C[(size_t)(r0+8)  * Nc + cc] = v1;
        }
    }
    #undef ISSUE_STAGE
}

// ---------------- spatial attention: softmax over P within (b,t,h) ----------------
__global__ void __launch_bounds__(256) spatial_attn_kernel(
    const float* __restrict__ Q, const float* __restrict__ K,
    const float* __restrict__ V, float* __restrict__ O)
{
    const int bt = blockIdx.x;
    const int h  = blockIdx.y;
    extern __shared__ float sm[];
    float* Ks = sm;                // [256][64]
    float* Vs = sm + PP_*DD_;      // [256][64]

    const int tid = threadIdx.x;
    const size_t base = (size_t)bt * PP_ * EE_ + h * DD_;

    for (int idx = tid; idx < PP_*DD_; idx += 256) {
        int p = idx >> 6, d = idx & 63;
        size_t g = base + (size_t)p * EE_ + d;
        Ks[idx] = K[g];
        Vs[idx] = V[g];
    }
    __syncthreads();

    float qf[DD_];
    const float* qp = Q + base + (size_t)tid * EE_;
    #pragma unroll
    for (int d4 = 0; d4 < DD_/4; d4++) {
        float4 t = *(const float4*)(qp + d4*4);
        qf[d4*4+0]=t.x; qf[d4*4+1]=t.y; qf[d4*4+2]=t.z; qf[d4*4+3]=t.w;
    }

    float m = -1e30f, l = 0.f;
    float acc[DD_];
    #pragma unroll
    for (int d = 0; d < DD_; d++) acc[d] = 0.f;

    for (int j = 0; j < PP_; j++) {
        const float4* kj = (const float4*)(Ks + j*DD_);
        float s = 0.f;
        #pragma unroll
        for (int d4 = 0; d4 < DD_/4; d4++) {
            float4 kv = kj[d4];
            s = fmaf(qf[d4*4+0], kv.x, s);
            s = fmaf(qf[d4*4+1], kv.y, s);
            s = fmaf(qf[d4*4+2], kv.z, s);
            s = fmaf(qf[d4*4+3], kv.w, s);
        }
        s *= SCALE_;
        float mn = fmaxf(m, s);
        float c  = __expf(m - mn);
        float pj = __expf(s - mn);
        l = l * c + pj;
        const float4* vj = (const float4*)(Vs + j*DD_);
        #pragma unroll
        for (int d4 = 0; d4 < DD_/4; d4++) {
            float4 vv = vj[d4];
            acc[d4*4+0] = fmaf(acc[d4*4+0], c, pj*vv.x);
            acc[d4*4+1] = fmaf(acc[d4*4+1], c, pj*vv.y);
            acc[d4*4+2] = fmaf(acc[d4*4+2], c, pj*vv.z);
            acc[d4*4+3] = fmaf(acc[d4*4+3], c, pj*vv.w);
        }
        m = mn;
    }

    float invl = 1.0f / l;
    float* op = O + base + (size_t)tid * EE_;
    #pragma unroll
    for (int d4 = 0; d4 < DD_/4; d4++) {
        float4 v;
        v.x = acc[d4*4+0]*invl; v.y = acc[d4*4+1]*invl;
        v.z = acc[d4*4+2]*invl; v.w = acc[d4*4+3]*invl;
        *(float4*)(op + d4*4) = v;
    }
}

// ---------------- temporal attention: causal softmax over T within (b,p,h) --------
__global__ void __launch_bounds__(192) temporal_attn_kernel(
    const float* __restrict__ Q, const float* __restrict__ K,
    const float* __restrict__ V, float* __restrict__ O)
{
    const int bp = blockIdx.x;
    const int b = bp >> 8;
    const int p = bp & 255;
    extern __shared__ float sm[];
    float* Ks = sm;               // [16][768]
    float* Vs = sm + TT_*EE_;

    const int tid = threadIdx.x;
    for (int idx = tid; idx < TT_*EE_; idx += 192) {
        int t = idx / EE_;
        int e = idx - t*EE_;
        size_t g = ((size_t)(b*TT_ + t) * PP_ + p) * EE_ + e;
        Ks[idx] = K[g];
        Vs[idx] = V[g];
    }
    __syncthreads();

    const int h  = tid >> 4;      // 0..11
    const int tq = tid & 15;      // 0..15

    const size_t qoff = ((size_t)(b*TT_ + tq) * PP_ + p) * EE_ + h * DD_;
    float qf[DD_];
    #pragma unroll
    for (int d4 = 0; d4 < DD_/4; d4++) {
        float4 t4 = *(const float4*)(Q + qoff + d4*4);
        qf[d4*4+0]=t4.x; qf[d4*4+1]=t4.y; qf[d4*4+2]=t4.z; qf[d4*4+3]=t4.w;
    }

    float sc[TT_];
    float m = -1e30f;
    #pragma unroll
    for (int s_ = 0; s_ < TT_; s_++) {
        const float* kr = Ks + s_*EE_ + h*DD_;
        float s = 0.f;
        #pragma unroll
        for (int d = 0; d < DD_; d++) s = fmaf(qf[d], kr[d], s);
        s *= SCALE_;
        if (s_ > tq) s = -1e30f;    // causal mask
        sc[s_] = s;
        m = fmaxf(m, s);
    }
    float l = 0.f;
    #pragma unroll
    for (int s_ = 0; s_ < TT_; s_++) {
        sc[s_] = __expf(sc[s_] - m);
        l += sc[s_];
    }
    float inv = 1.0f / l;

    float acc[DD_];
    #pragma unroll
    for (int d = 0; d < DD_; d++) acc[d] = 0.f;
    #pragma unroll
    for (int s_ = 0; s_ < TT_; s_++) {
        const float* vr = Vs + s_*EE_ + h*DD_;
        float w = sc[s_];
        #pragma unroll
        for (int d = 0; d < DD_; d++) acc[d] = fmaf(w, vr[d], acc[d]);
    }

    #pragma unroll
    for (int d4 = 0; d4 < DD_/4; d4++) {
        float4 v;
        v.x = acc[d4*4+0]*inv; v.y = acc[d4*4+1]*inv;
        v.z = acc[d4*4+2]*inv; v.w = acc[d4*4+3]*inv;
        *(float4*)(O + qoff + d4*4) = v;
    }
}

// ---------------- fused residual add + LayerNorm ----------------
__global__ void __launch_bounds__(256) add_ln_kernel(
    const float* __restrict__ x, const float* __restrict__ r,
    const float* __restrict__ gamma, const float* __restrict__ beta,
    float* __restrict__ out)
{
    const int row = blockIdx.x;
    const float* xr = x + (size_t)row * EE_;
    const float* rr = r + (size_t)row * EE_;

    float vals[3];
    float s = 0.f, ss = 0.f;
    #pragma unroll
    for (int i = 0; i < 3; i++) {
        int e = threadIdx.x + i*256;
        float v = xr[e] + rr[e];
        vals[i] = v;
        s += v;
        ss = fmaf(v, v, ss);
    }
    #pragma unroll
    for (int o = 16; o > 0; o >>= 1) {
        s  += __shfl_down_sync(0xffffffffu, s,  o);
        ss += __shfl_down_sync(0xffffffffu, ss, o);
    }
    __shared__ float reds[8], redss[8];
    int warp = threadIdx.x >> 5, lane = threadIdx.x & 31;
    if (lane == 0) { reds[warp] = s; redss[warp] = ss; }
    __syncthreads();
    float ts = 0.f, tss = 0.f;
    #pragma unroll
    for (int w = 0; w < 8; w++) { ts += reds[w]; tss += redss[w]; }

    const float invE = 1.0f / (float)EE_;
    float mean = ts * invE;
    float var  = tss * invE - mean * mean;
    float inv  = rsqrtf(var + EPS_);

    float* orow = out + (size_t)row * EE_;
    #pragma unroll
    for (int i = 0; i < 3; i++) {
        int e = threadIdx.x + i*256;
        orow[e] = (vals[i] - mean) * inv * gamma[e] + beta[e];
    }
}

// ---------------- host launcher ----------------
// canonical indices (dict order of setup_inputs)
enum { iX=0, iSQW, iSKW, iSVW, iSOW, iSQB, iSKB, iSVB, iSOB, iSG, iSB,
       iTQW, iTKW, iTVW, iTOW, iTQB, iTKB, iTVB, iTOB, iTG, iTB,
       iW1, iB1, iW2, iB2, iG, iBBb };

extern "C" void kernel_launch(void* const* d_in, const int* in_sizes, int n_in,
                              void* d_out, int out_size)
{
    // Resolve input ordering at runtime:
    //  dict order:      idx2 = sk_w (589824)
    //  signature order: idx2 = sq_b (768)
    static const int map_dict[27] = {0,1,2,3,4,5,6,7,8,9,10,11,12,13,14,15,16,17,18,19,20,21,22,23,24,25,26};
    static const int map_sig [27] = {0,1,3,5,7,2,4,6,8,9,10,11,13,15,17,12,14,16,18,19,20,21,22,23,24,25,26};
    const int* mp = (in_sizes[2] == 768) ? map_sig : map_dict;

    const float* in[27];
    for (int i = 0; i < 27; i++) in[i] = (const float*)d_in[mp[i]];

    float *gx, *gq, *gk, *gv, *gt, *gff;
    __nv_bfloat16 *ahi, *alo, *whi, *wlo;
    cudaGetSymbolAddress((void**)&gx,  g_x);
    cudaGetSymbolAddress((void**)&gq,  g_q);
    cudaGetSymbolAddress((void**)&gk,  g_k);
    cudaGetSymbolAddress((void**)&gv,  g_v);
    cudaGetSymbolAddress((void**)&gt,  g_t);
    cudaGetSymbolAddress((void**)&gff, g_ff);
    cudaGetSymbolAddress((void**)&ahi, g_ahi);
    cudaGetSymbolAddress((void**)&alo, g_alo);
    cudaGetSymbolAddress((void**)&whi, g_whi);
    cudaGetSymbolAddress((void**)&wlo, g_wlo);

    const int SPAT_SMEM = 2 * PP_ * DD_ * (int)sizeof(float);   // 128 KB
    const int TEMP_SMEM = 2 * TT_ * EE_ * (int)sizeof(float);   //  96 KB
    cudaFuncSetAttribute(spatial_attn_kernel,  cudaFuncAttributeMaxDynamicSharedMemorySize, SPAT_SMEM);
    cudaFuncSetAttribute(temporal_attn_kernel, cudaFuncAttributeMaxDynamicSharedMemorySize, TEMP_SMEM);
    cudaFuncSetAttribute(mma_gemm_kernel<false>, cudaFuncAttributeMaxDynamicSharedMemorySize, GSMEM_TOTAL_);
    cudaFuncSetAttribute(mma_gemm_kernel<true>,  cudaFuncAttributeMaxDynamicSharedMemorySize, GSMEM_TOTAL_);

    float* out = (float*)d_out;

    // ---- weight prep: transpose + split all 10 weight matrices ----
    const size_t offW[10] = {
        0, (size_t)WSZ_E, 2*(size_t)WSZ_E, 3*(size_t)WSZ_E,
        4*(size_t)WSZ_E, 5*(size_t)WSZ_E, 6*(size_t)WSZ_E, 7*(size_t)WSZ_E,
        8*(size_t)WSZ_E,
        8*(size_t)WSZ_E + (size_t)WSZ_F
    };
    const int srcW[10] = { iSQW, iSKW, iSVW, iSOW, iTQW, iTKW, iTVW, iTOW, iW1, iW2 };
    for (int wi = 0; wi < 10; wi++) {
        int K  = (wi == 9) ? DFF_ : EE_;
        int Nc = (wi == 8) ? DFF_ : EE_;
        dim3 g(Nc/32, K/32);
        wprep_kernel<<<g, 256>>>(in[srcW[wi]], whi + offW[wi], wlo + offW[wi], K, Nc);
    }

    const dim3 gemmBlk(256);
    const dim3 gE(EE_/128,  NN_/128);   // (6,128)
    const dim3 gF(DFF_/128, NN_/128);   // (24,128)
    const int NE = NN_*EE_;

    // ---- spatial block ----
    split_kernel<<<(NE+255)/256, 256>>>(in[iX], ahi, alo, NE);
    mma_gemm_kernel<false><<<gE, gemmBlk, GSMEM_TOTAL_>>>(ahi, alo, whi+offW[0], wlo+offW[0], in[iSQB], gq, EE_, EE_);
    mma_gemm_kernel<false><<<gE, gemmBlk, GSMEM_TOTAL_>>>(ahi, alo, whi+offW[1], wlo+offW[1], in[iSKB], gk, EE_, EE_);
    mma_gemm_kernel<false><<<gE, gemmBlk, GSMEM_TOTAL_>>>(ahi, alo, whi+offW[2], wlo+offW[2], in[iSVB], gv, EE_, EE_);
    spatial_attn_kernel<<<dim3(BB_*TT_, HH_), 256, SPAT_SMEM>>>(gq, gk, gv, gt);
    split_kernel<<<(NE+255)/256, 256>>>(gt, ahi, alo, NE);
    mma_gemm_kernel<false><<<gE, gemmBlk, GSMEM_TOTAL_>>>(ahi, alo, whi+offW[3], wlo+offW[3], in[iSOB], gq, EE_, EE_);
    add_ln_kernel<<<NN_, 256>>>(in[iX], gq, in[iSG], in[iSB], gx);

    // ---- temporal block ----
    split_kernel<<<(NE+255)/256, 256>>>(gx, ahi, alo, NE);
    mma_gemm_kernel<false><<<gE, gemmBlk, GSMEM_TOTAL_>>>(ahi, alo, whi+offW[4], wlo+offW[4], in[iTQB], gq, EE_, EE_);
    mma_gemm_kernel<false><<<gE, gemmBlk, GSMEM_TOTAL_>>>(ahi, alo, whi+offW[5], wlo+offW[5], in[iTKB], gk, EE_, EE_);
    mma_gemm_kernel<false><<<gE, gemmBlk, GSMEM_TOTAL_>>>(ahi, alo, whi+offW[6], wlo+offW[6], in[iTVB], gv, EE_, EE_);
    temporal_attn_kernel<<<BB_*PP_, 192, TEMP_SMEM>>>(gq, gk, gv, gt);
    split_kernel<<<(NE+255)/256, 256>>>(gt, ahi, alo, NE);
    mma_gemm_kernel<false><<<gE, gemmBlk, GSMEM_TOTAL_>>>(ahi, alo, whi+offW[7], wlo+offW[7], in[iTOB], gq, EE_, EE_);
    add_ln_kernel<<<NN_, 256>>>(gx, gq, in[iTG], in[iTB], gt);   // gt = x after LN2

    // ---- FFN ----
    split_kernel<<<(NE+255)/256, 256>>>(gt, ahi, alo, NE);
    mma_gemm_kernel<true ><<<gF, gemmBlk, GSMEM_TOTAL_>>>(ahi, alo, whi+offW[8], wlo+offW[8], in[iB1], gff, EE_, DFF_);
    split_kernel<<<(NN_*DFF_+255)/256, 256>>>(gff, ahi, alo, NN_*DFF_);
    mma_gemm_kernel<false><<<gE, gemmBlk, GSMEM_TOTAL_>>>(ahi, alo, whi+offW[9], wlo+offW[9], in[iB2], gq, DFF_, EE_);
    add_ln_kernel<<<NN_, 256>>>(gt, gq, in[iG], in[iBBb], out);
}

// round 12
// speedup vs baseline: 1.8818x; 1.1684x over previous
#include <cuda_runtime.h>
#include <cuda_bf16.h>
#include <math.h>
#include <stdint.h>

// ---------------- problem constants ----------------
#define BB_ 4
#define TT_ 16
#define PP_ 256
#define EE_ 768
#define HH_ 12
#define DD_ 64
#define DFF_ 3072
#define NN_ (BB_*TT_*PP_)          // 16384 tokens
#define SCALE_ 0.125f              // D^-0.5
#define EPS_ 1e-5f

// ---------------- helpers (base sm_103-safe PTX only) ----------------
__device__ __forceinline__ uint32_t smem_to_u32(const void* smem_ptr) {
    uint32_t addr;
    asm("{ .reg .u64 tmp; cvta.to.shared.u64 tmp, %1; cvt.u32.u64 %0, tmp; }"
        : "=r"(addr) : "l"(smem_ptr));
    return addr;
}
__device__ __forceinline__ void cpa16(uint32_t dst, const void* src) {
    asm volatile("cp.async.cg.shared.global [%0], [%1], 16;" :: "r"(dst), "l"(src));
}
#define CP_COMMIT() asm volatile("cp.async.commit_group;" ::: "memory")
#define CP_WAIT1()  asm volatile("cp.async.wait_group 1;" ::: "memory")

__device__ __forceinline__ void ldsm4(uint32_t* r, uint32_t addr) {
    asm volatile("ldmatrix.sync.aligned.m8n8.x4.shared.b16 {%0,%1,%2,%3}, [%4];"
        : "=r"(r[0]), "=r"(r[1]), "=r"(r[2]), "=r"(r[3]) : "r"(addr));
}
__device__ __forceinline__ void mma16816(float* d, const uint32_t* a, const uint32_t* b) {
    asm volatile(
        "mma.sync.aligned.m16n8k16.row.col.f32.bf16.bf16.f32 "
        "{%0,%1,%2,%3}, {%4,%5,%6,%7}, {%8,%9}, {%0,%1,%2,%3};"
        : "+f"(d[0]), "+f"(d[1]), "+f"(d[2]), "+f"(d[3])
        : "r"(a[0]), "r"(a[1]), "r"(a[2]), "r"(a[3]), "r"(b[0]), "r"(b[1]));
}
// split one float into bf16 hi + bf16 lo
__device__ __forceinline__ void fsplit(float v, __nv_bfloat16& h, __nv_bfloat16& l) {
    h = __float2bfloat16(v);
    l = __float2bfloat16(v - __bfloat162float(h));
}

// ---------------- scratch (static device arrays; no allocation) ----------------
__device__ float g_x [NN_*EE_];
__device__ float g_q [NN_*EE_];
__device__ float g_k [NN_*EE_];
__device__ float g_v [NN_*EE_];
__device__ float g_t [NN_*EE_];
// bf16 split activations: a = E-wide inputs, b = FFN hidden (DFF-wide)
__device__ __nv_bfloat16 g_ahi[(size_t)NN_*EE_];
__device__ __nv_bfloat16 g_alo[(size_t)NN_*EE_];
__device__ __nv_bfloat16 g_bhi[(size_t)NN_*DFF_];
__device__ __nv_bfloat16 g_blo[(size_t)NN_*DFF_];
// bf16 split transposed weights [Nc, K]: 8 x 768x768 + 2 x (768*3072)
#define WSZ_E (EE_*EE_)              // 589824
#define WSZ_F (EE_*DFF_)             // 2359296
#define WTOT  (8*WSZ_E + 2*WSZ_F)    // 9437184
__device__ __nv_bfloat16 g_whi[WTOT];
__device__ __nv_bfloat16 g_wlo[WTOT];

// ---------------- weight prep: transpose + hi/lo split ----------------
// W [K, Nc] fp32 -> Thi/Tlo [Nc, K] bf16
__global__ void __launch_bounds__(256) wprep_kernel(
    const float* __restrict__ W, __nv_bfloat16* __restrict__ Thi,
    __nv_bfloat16* __restrict__ Tlo, int K, int Nc)
{
    __shared__ float tile[32][33];
    const int tx = threadIdx.x & 31;
    const int ty = threadIdx.x >> 5;          // 0..7
    const int n0 = blockIdx.x * 32;
    const int k0 = blockIdx.y * 32;
    #pragma unroll
    for (int j = 0; j < 4; j++)
        tile[ty + 8*j][tx] = W[(size_t)(k0 + ty + 8*j) * Nc + n0 + tx];
    __syncthreads();
    #pragma unroll
    for (int j = 0; j < 4; j++) {
        float v = tile[tx][ty + 8*j];
        __nv_bfloat16 h, l;
        fsplit(v, h, l);
        size_t o = (size_t)(n0 + ty + 8*j) * K + k0 + tx;
        Thi[o] = h;
        Tlo[o] = l;
    }
}

// ---------------- activation split: fp32 -> hi/lo bf16 (only for input x) -------
__global__ void __launch_bounds__(256) split_kernel(
    const float* __restrict__ x, __nv_bfloat16* __restrict__ hi,
    __nv_bfloat16* __restrict__ lo, int n)
{
    int i = blockIdx.x * 256 + threadIdx.x;
    if (i < n) {
        __nv_bfloat16 h, l;
        fsplit(x[i], h, l);
        hi[i] = h;
        lo[i] = l;
    }
}

// ---------------- mma.sync GEMM: C = (Ahi+Alo)[M,K] @ (Whi+Wlo)^T + bias --------
// 128x128 CTA tile, BK=32, 256 threads (8 warps, 2x4), cp.async 2-stage pipeline,
// 2 CTAs/SM. Rows padded to 80B -> conflict-free non-trans ldmatrix for A and B.
// WRITE_SPLIT: epilogue emits bf16 hi/lo (for GEMM-chained consumers) instead of fp32.
#define AROW_  40
#define AROWB_ (AROW_*2)                // 80 bytes per padded row
#define MATB_  (128*AROWB_)             // 10240 bytes per matrix per stage
#define STG_B  (4*MATB_)                // 40960: Ahi, Alo, Bhi, Blo
#define NSTG_  2
#define GSMEM_TOTAL_ (NSTG_*STG_B)      // 81920 -> 2 CTAs/SM

__device__ __forceinline__ float gelu_exact(float x) {
    return 0.5f * x * (1.0f + erff(x * 0.70710678118654752f));
}

template<bool DO_GELU, bool WRITE_SPLIT>
__global__ void __launch_bounds__(256, 2) mma_gemm_kernel(
    const __nv_bfloat16* __restrict__ Ahi, const __nv_bfloat16* __restrict__ Alo,
    const __nv_bfloat16* __restrict__ Whi, const __nv_bfloat16* __restrict__ Wlo,
    const float* __restrict__ bias, float* __restrict__ C,
    __nv_bfloat16* __restrict__ Chi, __nv_bfloat16* __restrict__ Clo,
    int K, int Nc)
{
    extern __shared__ __align__(128) char smem[];
    const uint32_t sbase = smem_to_u32(smem);
    const int tid  = threadIdx.x;
    const int lane = tid & 31;
    const int wid  = tid >> 5;
    const int wm   = wid >> 2;          // 0..1
    const int wn   = wid & 3;           // 0..3
    const int bm   = blockIdx.y * 128;
    const int bn   = blockIdx.x * 128;
    const int nchunk = K >> 5;          // K/32

    // cp.async assignment: thread -> one row, two 16B chunks
    const int lrow = tid >> 1;          // 0..127
    const int cbc  = (tid & 1) * 2;     // chunk base 0 or 2
    const __nv_bfloat16* gA0 = Ahi + (size_t)(bm + lrow) * K + cbc * 8;
    const __nv_bfloat16* gA1 = Alo + (size_t)(bm + lrow) * K + cbc * 8;
    const __nv_bfloat16* gB0 = Whi + (size_t)(bn + lrow) * K + cbc * 8;
    const __nv_bfloat16* gB1 = Wlo + (size_t)(bn + lrow) * K + cbc * 8;
    const uint32_t dstb = (uint32_t)lrow * AROWB_ + cbc * 16;

    #define ISSUE_STAGE(s, kc) do { \
        uint32_t st_ = sbase + (s) * STG_B + dstb; \
        cpa16(st_,               gA0 + (kc)); cpa16(st_ + 16,               gA0 + (kc) + 8); \
        cpa16(st_ +   MATB_,     gA1 + (kc)); cpa16(st_ +   MATB_ + 16,     gA1 + (kc) + 8); \
        cpa16(st_ + 2*MATB_,     gB0 + (kc)); cpa16(st_ + 2*MATB_ + 16,     gB0 + (kc) + 8); \
        cpa16(st_ + 3*MATB_,     gB1 + (kc)); cpa16(st_ + 3*MATB_ + 16,     gB1 + (kc) + 8); \
    } while (0)

    ISSUE_STAGE(0, 0);  CP_COMMIT();
    ISSUE_STAGE(1, 32); CP_COMMIT();

    float acc[4][4][4];
    #pragma unroll
    for (int mi = 0; mi < 4; mi++)
        #pragma unroll
        for (int nj = 0; nj < 4; nj++)
            #pragma unroll
            for (int r = 0; r < 4; r++) acc[mi][nj][r] = 0.f;

    // ldmatrix per-lane source rows (non-trans for BOTH operands)
    const uint32_t a_row = (uint32_t)(wm*64 + (lane & 15)) * AROWB_;
    const uint32_t a_kh  = (uint32_t)(lane >> 4) * 16;
    const uint32_t b_row = (uint32_t)(wn*32 + ((lane >> 4) << 3) + (lane & 7)) * AROWB_;
    const uint32_t b_kh  = (uint32_t)((lane >> 3) & 1) * 16;

    for (int c = 0; c < nchunk; ++c) {
        CP_WAIT1();
        __syncthreads();

        const uint32_t st = sbase + (c & 1) * STG_B;
        #pragma unroll
        for (int ks = 0; ks < 2; ks++) {
            const uint32_t akb = (uint32_t)ks*32 + a_kh;
            const uint32_t bkb = (uint32_t)ks*32 + b_kh;
            uint32_t bh[4][2], bl[4][2];
            #pragma unroll
            for (int np = 0; np < 2; np++) {
                uint32_t r4[4];
                ldsm4(r4, st + 2*MATB_ + b_row + (uint32_t)np*16*AROWB_ + bkb);
                bh[np*2][0] = r4[0]; bh[np*2][1] = r4[1];
                bh[np*2+1][0] = r4[2]; bh[np*2+1][1] = r4[3];
                ldsm4(r4, st + 3*MATB_ + b_row + (uint32_t)np*16*AROWB_ + bkb);
                bl[np*2][0] = r4[0]; bl[np*2][1] = r4[1];
                bl[np*2+1][0] = r4[2]; bl[np*2+1][1] = r4[3];
            }
            #pragma unroll
            for (int mi = 0; mi < 4; mi++) {
                uint32_t ah[4], al[4];
                ldsm4(ah, st +         a_row + (uint32_t)mi*16*AROWB_ + akb);
                ldsm4(al, st + MATB_ + a_row + (uint32_t)mi*16*AROWB_ + akb);
                #pragma unroll
                for (int nj = 0; nj < 4; nj++) {
                    mma16816(acc[mi][nj], ah, bh[nj]);   // hi*hi
                    mma16816(acc[mi][nj], ah, bl[nj]);   // hi*lo
                    mma16816(acc[mi][nj], al, bh[nj]);   // lo*hi
                }
            }
        }
        __syncthreads();   // buffer (c&1) free for reuse
        if (c + 2 < nchunk) { ISSUE_STAGE((c & 1), (c + 2) * 32); }
        CP_COMMIT();       // uniform ledger (empty group near tail)
    }

    // epilogue
    #pragma unroll
    for (int mi = 0; mi < 4; mi++) {
        const int r0 = bm + wm*64 + mi*16 + (lane >> 2);
        #pragma unroll
        for (int nj = 0; nj < 4; nj++) {
            const int cc = bn + wn*32 + nj*8 + (lane & 3)*2;
            float b0 = bias[cc], b1 = bias[cc+1];
            float v00 = acc[mi][nj][0] + b0, v01 = acc[mi][nj][1] + b1;
            float v10 = acc[mi][nj][2] + b0, v11 = acc[mi][nj][3] + b1;
            if (DO_GELU) {
                v00 = gelu_exact(v00); v01 = gelu_exact(v01);
                v10 = gelu_exact(v10); v11 = gelu_exact(v11);
            }
            if (WRITE_SPLIT) {
                __nv_bfloat16 h0,l0,h1,l1;
                fsplit(v00,h0,l0); fsplit(v01,h1,l1);
                *(__nv_bfloat162*)(Chi + (size_t)r0*Nc + cc) = __nv_bfloat162(h0,h1);
                *(__nv_bfloat162*)(Clo + (size_t)r0*Nc + cc) = __nv_bfloat162(l0,l1);
                fsplit(v10,h0,l0); fsplit(v11,h1,l1);
                *(__nv_bfloat162*)(Chi + (size_t)(r0+8)*Nc + cc) = __nv_bfloat162(h0,h1);
                *(__nv_bfloat162*)(Clo + (size_t)(r0+8)*Nc + cc) = __nv_bfloat162(l0,l1);
            } else {
                float2 w0; w0.x = v00; w0.y = v01;
                float2 w1; w1.x = v10; w1.y = v11;
                *(float2*)&C[(size_t)r0     * Nc + cc] = w0;
                *(float2*)&C[(size_t)(r0+8) * Nc + cc] = w1;
            }
        }
    }
    #undef ISSUE_STAGE
}

// ---------------- spatial attention (emits bf16 hi/lo directly) -----------------
__global__ void __launch_bounds__(256) spatial_attn_kernel(
    const float* __restrict__ Q, const float* __restrict__ K,
    const float* __restrict__ V,
    __nv_bfloat16* __restrict__ Ohi, __nv_bfloat16* __restrict__ Olo)
{
    const int bt = blockIdx.x;
    const int h  = blockIdx.y;
    extern __shared__ float sm[];
    float* Ks = sm;                // [256][64]
    float* Vs = sm + PP_*DD_;      // [256][64]

    const int tid = threadIdx.x;
    const size_t base = (size_t)bt * PP_ * EE_ + h * DD_;

    for (int idx = tid; idx < PP_*DD_; idx += 256) {
        int p = idx >> 6, d = idx & 63;
        size_t g = base + (size_t)p * EE_ + d;
        Ks[idx] = K[g];
        Vs[idx] = V[g];
    }
    __syncthreads();

    float qf[DD_];
    const float* qp = Q + base + (size_t)tid * EE_;
    #pragma unroll
    for (int d4 = 0; d4 < DD_/4; d4++) {
        float4 t = *(const float4*)(qp + d4*4);
        qf[d4*4+0]=t.x; qf[d4*4+1]=t.y; qf[d4*4+2]=t.z; qf[d4*4+3]=t.w;
    }

    float m = -1e30f, l = 0.f;
    float acc[DD_];
    #pragma unroll
    for (int d = 0; d < DD_; d++) acc[d] = 0.f;

    for (int j = 0; j < PP_; j++) {
        const float4* kj = (const float4*)(Ks + j*DD_);
        float s = 0.f;
        #pragma unroll
        for (int d4 = 0; d4 < DD_/4; d4++) {
            float4 kv = kj[d4];
            s = fmaf(qf[d4*4+0], kv.x, s);
            s = fmaf(qf[d4*4+1], kv.y, s);
            s = fmaf(qf[d4*4+2], kv.z, s);
            s = fmaf(qf[d4*4+3], kv.w, s);
        }
        s *= SCALE_;
        float mn = fmaxf(m, s);
        float c  = __expf(m - mn);
        float pj = __expf(s - mn);
        l = l * c + pj;
        const float4* vj = (const float4*)(Vs + j*DD_);
        #pragma unroll
        for (int d4 = 0; d4 < DD_/4; d4++) {
            float4 vv = vj[d4];
            acc[d4*4+0] = fmaf(acc[d4*4+0], c, pj*vv.x);
            acc[d4*4+1] = fmaf(acc[d4*4+1], c, pj*vv.y);
            acc[d4*4+2] = fmaf(acc[d4*4+2], c, pj*vv.z);
            acc[d4*4+3] = fmaf(acc[d4*4+3], c, pj*vv.w);
        }
        m = mn;
    }

    float invl = 1.0f / l;
    const size_t ob = base + (size_t)tid * EE_;
    #pragma unroll
    for (int d2 = 0; d2 < DD_/2; d2++) {
        float a0 = acc[d2*2+0]*invl, a1 = acc[d2*2+1]*invl;
        __nv_bfloat16 h0,l0,h1,l1;
        fsplit(a0,h0,l0); fsplit(a1,h1,l1);
        *(__nv_bfloat162*)(Ohi + ob + d2*2) = __nv_bfloat162(h0,h1);
        *(__nv_bfloat162*)(Olo + ob + d2*2) = __nv_bfloat162(l0,l1);
    }
}

// ---------------- temporal attention (emits bf16 hi/lo directly) ----------------
__global__ void __launch_bounds__(192) temporal_attn_kernel(
    const float* __restrict__ Q, const float* __restrict__ K,
    const float* __restrict__ V,
    __nv_bfloat16* __restrict__ Ohi, __nv_bfloat16* __restrict__ Olo)
{
    const int bp = blockIdx.x;
    const int b = bp >> 8;
    const int p = bp & 255;
    extern __shared__ float sm[];
    float* Ks = sm;               // [16][768]
    float* Vs = sm + TT_*EE_;

    const int tid = threadIdx.x;
    for (int idx = tid; idx < TT_*EE_; idx += 192) {
        int t = idx / EE_;
        int e = idx - t*EE_;
        size_t g = ((size_t)(b*TT_ + t) * PP_ + p) * EE_ + e;
        Ks[idx] = K[g];
        Vs[idx] = V[g];
    }
    __syncthreads();

    const int h  = tid >> 4;      // 0..11
    const int tq = tid & 15;      // 0..15

    const size_t qoff = ((size_t)(b*TT_ + tq) * PP_ + p) * EE_ + h * DD_;
    float qf[DD_];
    #pragma unroll
    for (int d4 = 0; d4 < DD_/4; d4++) {
        float4 t4 = *(const float4*)(Q + qoff + d4*4);
        qf[d4*4+0]=t4.x; qf[d4*4+1]=t4.y; qf[d4*4+2]=t4.z; qf[d4*4+3]=t4.w;
    }

    float sc[TT_];
    float m = -1e30f;
    #pragma unroll
    for (int s_ = 0; s_ < TT_; s_++) {
        const float* kr = Ks + s_*EE_ + h*DD_;
        float s = 0.f;
        #pragma unroll
        for (int d = 0; d < DD_; d++) s = fmaf(qf[d], kr[d], s);
        s *= SCALE_;
        if (s_ > tq) s = -1e30f;    // causal mask
        sc[s_] = s;
        m = fmaxf(m, s);
    }
    float l = 0.f;
    #pragma unroll
    for (int s_ = 0; s_ < TT_; s_++) {
        sc[s_] = __expf(sc[s_] - m);
        l += sc[s_];
    }
    float inv = 1.0f / l;

    float acc[DD_];
    #pragma unroll
    for (int d = 0; d < DD_; d++) acc[d] = 0.f;
    #pragma unroll
    for (int s_ = 0; s_ < TT_; s_++) {
        const float* vr = Vs + s_*EE_ + h*DD_;
        float w = sc[s_];
        #pragma unroll
        for (int d = 0; d < DD_; d++) acc[d] = fmaf(w, vr[d], acc[d]);
    }

    #pragma unroll
    for (int d2 = 0; d2 < DD_/2; d2++) {
        float a0 = acc[d2*2+0]*inv, a1 = acc[d2*2+1]*inv;
        __nv_bfloat16 h0,l0,h1,l1;
        fsplit(a0,h0,l0); fsplit(a1,h1,l1);
        *(__nv_bfloat162*)(Ohi + qoff + d2*2) = __nv_bfloat162(h0,h1);
        *(__nv_bfloat162*)(Olo + qoff + d2*2) = __nv_bfloat162(l0,l1);
    }
}

// ---------------- fused residual add + LayerNorm (+ optional hi/lo emit) --------
template<bool EMIT_SPLIT>
__global__ void __launch_bounds__(256) add_ln_kernel(
    const float* __restrict__ x, const float* __restrict__ r,
    const float* __restrict__ gamma, const float* __restrict__ beta,
    float* __restrict__ out,
    __nv_bfloat16* __restrict__ Ohi, __nv_bfloat16* __restrict__ Olo)
{
    const int row = blockIdx.x;
    const float* xr = x + (size_t)row * EE_;
    const float* rr = r + (size_t)row * EE_;

    float vals[3];
    float s = 0.f, ss = 0.f;
    #pragma unroll
    for (int i = 0; i < 3; i++) {
        int e = threadIdx.x + i*256;
        float v = xr[e] + rr[e];
        vals[i] = v;
        s += v;
        ss = fmaf(v, v, ss);
    }
    #pragma unroll
    for (int o = 16; o > 0; o >>= 1) {
        s  += __shfl_down_sync(0xffffffffu, s,  o);
        ss += __shfl_down_sync(0xffffffffu, ss, o);
    }
    __shared__ float reds[8], redss[8];
    int warp = threadIdx.x >> 5, lane = threadIdx.x & 31;
    if (lane == 0) { reds[warp] = s; redss[warp] = ss; }
    __syncthreads();
    float ts = 0.f, tss = 0.f;
    #pragma unroll
    for (int w = 0; w < 8; w++) { ts += reds[w]; tss += redss[w]; }

    const float invE = 1.0f / (float)EE_;
    float mean = ts * invE;
    float var  = tss * invE - mean * mean;
    float inv  = rsqrtf(var + EPS_);

    float* orow = out + (size_t)row * EE_;
    #pragma unroll
    for (int i = 0; i < 3; i++) {
        int e = threadIdx.x + i*256;
        float o = (vals[i] - mean) * inv * gamma[e] + beta[e];
        orow[e] = o;
        if (EMIT_SPLIT) {
            __nv_bfloat16 h, l;
            fsplit(o, h, l);
            Ohi[(size_t)row*EE_ + e] = h;
            Olo[(size_t)row*EE_ + e] = l;
        }
    }
}

// ---------------- host launcher ----------------
// canonical indices (dict order of setup_inputs)
enum { iX=0, iSQW, iSKW, iSVW, iSOW, iSQB, iSKB, iSVB, iSOB, iSG, iSB,
       iTQW, iTKW, iTVW, iTOW, iTQB, iTKB, iTVB, iTOB, iTG, iTB,
       iW1, iB1, iW2, iB2, iG, iBBb };

extern "C" void kernel_launch(void* const* d_in, const int* in_sizes, int n_in,
                              void* d_out, int out_size)
{
    // Resolve input ordering at runtime:
    //  dict order:      idx2 = sk_w (589824)
    //  signature order: idx2 = sq_b (768)
    static const int map_dict[27] = {0,1,2,3,4,5,6,7,8,9,10,11,12,13,14,15,16,17,18,19,20,21,22,23,24,25,26};
    static const int map_sig [27] = {0,1,3,5,7,2,4,6,8,9,10,11,13,15,17,12,14,16,18,19,20,21,22,23,24,25,26};
    const int* mp = (in_sizes[2] == 768) ? map_sig : map_dict;

    const float* in[27];
    for (int i = 0; i < 27; i++) in[i] = (const float*)d_in[mp[i]];

    float *gx, *gq, *gk, *gv, *gt;
    __nv_bfloat16 *ahi, *alo, *bhi, *blo, *whi, *wlo;
    cudaGetSymbolAddress((void**)&gx,  g_x);
    cudaGetSymbolAddress((void**)&gq,  g_q);
    cudaGetSymbolAddress((void**)&gk,  g_k);
    cudaGetSymbolAddress((void**)&gv,  g_v);
    cudaGetSymbolAddress((void**)&gt,  g_t);
    cudaGetSymbolAddress((void**)&ahi, g_ahi);
    cudaGetSymbolAddress((void**)&alo, g_alo);
    cudaGetSymbolAddress((void**)&bhi, g_bhi);
    cudaGetSymbolAddress((void**)&blo, g_blo);
    cudaGetSymbolAddress((void**)&whi, g_whi);
    cudaGetSymbolAddress((void**)&wlo, g_wlo);

    const int SPAT_SMEM = 2 * PP_ * DD_ * (int)sizeof(float);   // 128 KB
    const int TEMP_SMEM = 2 * TT_ * EE_ * (int)sizeof(float);   //  96 KB
    cudaFuncSetAttribute(spatial_attn_kernel,  cudaFuncAttributeMaxDynamicSharedMemorySize, SPAT_SMEM);
    cudaFuncSetAttribute(temporal_attn_kernel, cudaFuncAttributeMaxDynamicSharedMemorySize, TEMP_SMEM);
    cudaFuncSetAttribute((const void*)mma_gemm_kernel<false,false>, cudaFuncAttributeMaxDynamicSharedMemorySize, GSMEM_TOTAL_);
    cudaFuncSetAttribute((const void*)mma_gemm_kernel<true,true>,   cudaFuncAttributeMaxDynamicSharedMemorySize, GSMEM_TOTAL_);

    float* out = (float*)d_out;

    // ---- weight prep: transpose + split all 10 weight matrices ----
    const size_t offW[10] = {
        0, (size_t)WSZ_E, 2*(size_t)WSZ_E, 3*(size_t)WSZ_E,
        4*(size_t)WSZ_E, 5*(size_t)WSZ_E, 6*(size_t)WSZ_E, 7*(size_t)WSZ_E,
        8*(size_t)WSZ_E,
        8*(size_t)WSZ_E + (size_t)WSZ_F
    };
    const int srcW[10] = { iSQW, iSKW, iSVW, iSOW, iTQW, iTKW, iTVW, iTOW, iW1, iW2 };
    for (int wi = 0; wi < 10; wi++) {
        int K  = (wi == 9) ? DFF_ : EE_;
        int Nc = (wi == 8) ? DFF_ : EE_;
        dim3 g(Nc/32, K/32);
        wprep_kernel<<<g, 256>>>(in[srcW[wi]], whi + offW[wi], wlo + offW[wi], K, Nc);
    }

    const dim3 gemmBlk(256);
    const dim3 gE(EE_/128,  NN_/128);   // (6,128)
    const dim3 gF(DFF_/128, NN_/128);   // (24,128)
    const int NE = NN_*EE_;

    #define GEMM_F(grid, A0, A1, W0, W1, B, Cout, Kd, Nd) \
        mma_gemm_kernel<false,false><<<grid, gemmBlk, GSMEM_TOTAL_>>>( \
            A0, A1, W0, W1, B, Cout, (\
            __nv_bfloat16*)nullptr, (__nv_bfloat16*)nullptr, Kd, Nd)

    // ---- spatial block ----
    split_kernel<<<(NE+255)/256, 256>>>(in[iX], ahi, alo, NE);
    GEMM_F(gE, ahi, alo, whi+offW[0], wlo+offW[0], in[iSQB], gq, EE_, EE_);
    GEMM_F(gE, ahi, alo, whi+offW[1], wlo+offW[1], in[iSKB], gk, EE_, EE_);
    GEMM_F(gE, ahi, alo, whi+offW[2], wlo+offW[2], in[iSVB], gv, EE_, EE_);
    spatial_attn_kernel<<<dim3(BB_*TT_, HH_), 256, SPAT_SMEM>>>(gq, gk, gv, ahi, alo);
    GEMM_F(gE, ahi, alo, whi+offW[3], wlo+offW[3], in[iSOB], gq, EE_, EE_);
    add_ln_kernel<true><<<NN_, 256>>>(in[iX], gq, in[iSG], in[iSB], gx, ahi, alo);

    // ---- temporal block ----
    GEMM_F(gE, ahi, alo, whi+offW[4], wlo+offW[4], in[iTQB], gq, EE_, EE_);
    GEMM_F(gE, ahi, alo, whi+offW[5], wlo+offW[5], in[iTKB], gk, EE_, EE_);
    GEMM_F(gE, ahi, alo, whi+offW[6], wlo+offW[6], in[iTVB], gv, EE_, EE_);
    temporal_attn_kernel<<<BB_*PP_, 192, TEMP_SMEM>>>(gq, gk, gv, ahi, alo);
    GEMM_F(gE, ahi, alo, whi+offW[7], wlo+offW[7], in[iTOB], gq, EE_, EE_);
    add_ln_kernel<true><<<NN_, 256>>>(gx, gq, in[iTG], in[iTB], gt, ahi, alo);

    // ---- FFN ----
    mma_gemm_kernel<true,true><<<gF, gemmBlk, GSMEM_TOTAL_>>>(
        ahi, alo, whi+offW[8], wlo+offW[8], in[iB1],
        (float*)nullptr, bhi, blo, EE_, DFF_);
    GEMM_F(gE, bhi, blo, whi+offW[9], wlo+offW[9], in[iB2], gq, DFF_, EE_);
    add_ln_kernel<false><<<NN_, 256>>>(gt, gq, in[iG], in[iBBb], out,
        (__nv_bfloat16*)nullptr, (__nv_bfloat16*)nullptr);

    #undef GEMM_F
}

// round 13
// speedup vs baseline: 1.8825x; 1.0004x over previous
#include <cuda_runtime.h>
#include <cuda_bf16.h>
#include <math.h>
#include <stdint.h>

// ---------------- problem constants ----------------
#define BB_ 4
#define TT_ 16
#define PP_ 256
#define EE_ 768
#define HH_ 12
#define DD_ 64
#define DFF_ 3072
#define NN_ (BB_*TT_*PP_)          // 16384 tokens
#define SCALE_ 0.125f              // D^-0.5
#define EPS_ 1e-5f

// ---------------- helpers (base sm_103-safe PTX only) ----------------
__device__ __forceinline__ uint32_t smem_to_u32(const void* smem_ptr) {
    uint32_t addr;
    asm("{ .reg .u64 tmp; cvta.to.shared.u64 tmp, %1; cvt.u32.u64 %0, tmp; }"
        : "=r"(addr) : "l"(smem_ptr));
    return addr;
}
__device__ __forceinline__ void cpa16(uint32_t dst, const void* src) {
    asm volatile("cp.async.cg.shared.global [%0], [%1], 16;" :: "r"(dst), "l"(src));
}
#define CP_COMMIT() asm volatile("cp.async.commit_group;" ::: "memory")
#define CP_WAIT1()  asm volatile("cp.async.wait_group 1;" ::: "memory")

__device__ __forceinline__ void ldsm4(uint32_t* r, uint32_t addr) {
    asm volatile("ldmatrix.sync.aligned.m8n8.x4.shared.b16 {%0,%1,%2,%3}, [%4];"
        : "=r"(r[0]), "=r"(r[1]), "=r"(r[2]), "=r"(r[3]) : "r"(addr));
}
__device__ __forceinline__ void mma16816(float* d, const uint32_t* a, const uint32_t* b) {
    asm volatile(
        "mma.sync.aligned.m16n8k16.row.col.f32.bf16.bf16.f32 "
        "{%0,%1,%2,%3}, {%4,%5,%6,%7}, {%8,%9}, {%0,%1,%2,%3};"
        : "+f"(d[0]), "+f"(d[1]), "+f"(d[2]), "+f"(d[3])
        : "r"(a[0]), "r"(a[1]), "r"(a[2]), "r"(a[3]), "r"(b[0]), "r"(b[1]));
}
// split one float into bf16 hi + bf16 lo
__device__ __forceinline__ void fsplit(float v, __nv_bfloat16& h, __nv_bfloat16& l) {
    h = __float2bfloat16(v);
    l = __float2bfloat16(v - __bfloat162float(h));
}

// ---------------- scratch (static device arrays; no allocation) ----------------
__device__ float g_x [NN_*EE_];
__device__ float g_q [NN_*EE_];
__device__ float g_k [NN_*EE_];
__device__ float g_v [NN_*EE_];
__device__ float g_t [NN_*EE_];
// bf16 split activations: a = E-wide inputs, b = FFN hidden (DFF-wide)
__device__ __nv_bfloat16 g_ahi[(size_t)NN_*EE_];
__device__ __nv_bfloat16 g_alo[(size_t)NN_*EE_];
__device__ __nv_bfloat16 g_bhi[(size_t)NN_*DFF_];
__device__ __nv_bfloat16 g_blo[(size_t)NN_*DFF_];
// bf16 split transposed weights [Nc, K]: 8 x 768x768 + 2 x (768*3072)
#define WSZ_E (EE_*EE_)              // 589824
#define WSZ_F (EE_*DFF_)             // 2359296
#define WTOT  (8*WSZ_E + 2*WSZ_F)    // 9437184
__device__ __nv_bfloat16 g_whi[WTOT];
__device__ __nv_bfloat16 g_wlo[WTOT];

// ---------------- weight prep: transpose + hi/lo split ----------------
// W [K, Nc] fp32 -> Thi/Tlo [Nc, K] bf16  (single weight)
__global__ void __launch_bounds__(256) wprep_kernel(
    const float* __restrict__ W, __nv_bfloat16* __restrict__ Thi,
    __nv_bfloat16* __restrict__ Tlo, int K, int Nc)
{
    __shared__ float tile[32][33];
    const int tx = threadIdx.x & 31;
    const int ty = threadIdx.x >> 5;          // 0..7
    const int n0 = blockIdx.x * 32;
    const int k0 = blockIdx.y * 32;
    #pragma unroll
    for (int j = 0; j < 4; j++)
        tile[ty + 8*j][tx] = W[(size_t)(k0 + ty + 8*j) * Nc + n0 + tx];
    __syncthreads();
    #pragma unroll
    for (int j = 0; j < 4; j++) {
        float v = tile[tx][ty + 8*j];
        __nv_bfloat16 h, l;
        fsplit(v, h, l);
        size_t o = (size_t)(n0 + ty + 8*j) * K + k0 + tx;
        Thi[o] = h;
        Tlo[o] = l;
    }
}

// batched version for the 8 E x E weights (blockIdx.z selects the weight)
__global__ void __launch_bounds__(256) wprep8_kernel(
    const float* __restrict__ W0, const float* __restrict__ W1,
    const float* __restrict__ W2, const float* __restrict__ W3,
    const float* __restrict__ W4, const float* __restrict__ W5,
    const float* __restrict__ W6, const float* __restrict__ W7,
    __nv_bfloat16* __restrict__ Thi, __nv_bfloat16* __restrict__ Tlo)
{
    const float* Ws[8] = { W0, W1, W2, W3, W4, W5, W6, W7 };
    const int wi = blockIdx.z;
    const float* W = Ws[wi];
    __nv_bfloat16* Th = Thi + (size_t)wi * WSZ_E;
    __nv_bfloat16* Tl = Tlo + (size_t)wi * WSZ_E;

    __shared__ float tile[32][33];
    const int tx = threadIdx.x & 31;
    const int ty = threadIdx.x >> 5;
    const int n0 = blockIdx.x * 32;
    const int k0 = blockIdx.y * 32;
    #pragma unroll
    for (int j = 0; j < 4; j++)
        tile[ty + 8*j][tx] = W[(size_t)(k0 + ty + 8*j) * EE_ + n0 + tx];
    __syncthreads();
    #pragma unroll
    for (int j = 0; j < 4; j++) {
        float v = tile[tx][ty + 8*j];
        __nv_bfloat16 h, l;
        fsplit(v, h, l);
        size_t o = (size_t)(n0 + ty + 8*j) * EE_ + k0 + tx;
        Th[o] = h;
        Tl[o] = l;
    }
}

// ---------------- activation split: fp32 -> hi/lo bf16 (only for input x) -------
__global__ void __launch_bounds__(256) split_kernel(
    const float* __restrict__ x, __nv_bfloat16* __restrict__ hi,
    __nv_bfloat16* __restrict__ lo, int n)
{
    int i = blockIdx.x * 256 + threadIdx.x;
    if (i < n) {
        __nv_bfloat16 h, l;
        fsplit(x[i], h, l);
        hi[i] = h;
        lo[i] = l;
    }
}

// ---------------- mma.sync GEMM: C = (Ahi+Alo)[M,K] @ (Whi+Wlo)^T + bias --------
// 128x128 CTA tile, BK=32, 256 threads (8 warps, 2x4), cp.async 2-stage pipeline,
// 2 CTAs/SM. Rows padded to 80B -> conflict-free non-trans ldmatrix for A and B.
// Inner loop is PASS-MAJOR over nj: consecutive asm-volatile mmas never share an
// accumulator (reuse distance 4), hiding HMMA result latency.
#define AROW_  40
#define AROWB_ (AROW_*2)                // 80 bytes per padded row
#define MATB_  (128*AROWB_)             // 10240 bytes per matrix per stage
#define STG_B  (4*MATB_)                // 40960: Ahi, Alo, Bhi, Blo
#define NSTG_  2
#define GSMEM_TOTAL_ (NSTG_*STG_B)      // 81920 -> 2 CTAs/SM

__device__ __forceinline__ float gelu_exact(float x) {
    return 0.5f * x * (1.0f + erff(x * 0.70710678118654752f));
}

template<bool DO_GELU, bool WRITE_SPLIT>
__global__ void __launch_bounds__(256, 2) mma_gemm_kernel(
    const __nv_bfloat16* __restrict__ Ahi, const __nv_bfloat16* __restrict__ Alo,
    const __nv_bfloat16* __restrict__ Whi, const __nv_bfloat16* __restrict__ Wlo,
    const float* __restrict__ bias, float* __restrict__ C,
    __nv_bfloat16* __restrict__ Chi, __nv_bfloat16* __restrict__ Clo,
    int K, int Nc)
{
    extern __shared__ __align__(128) char smem[];
    const uint32_t sbase = smem_to_u32(smem);
    const int tid  = threadIdx.x;
    const int lane = tid & 31;
    const int wid  = tid >> 5;
    const int wm   = wid >> 2;          // 0..1
    const int wn   = wid & 3;           // 0..3
    const int bm   = blockIdx.y * 128;
    const int bn   = blockIdx.x * 128;
    const int nchunk = K >> 5;          // K/32

    // cp.async assignment: thread -> one row, two 16B chunks
    const int lrow = tid >> 1;          // 0..127
    const int cbc  = (tid & 1) * 2;     // chunk base 0 or 2
    const __nv_bfloat16* gA0 = Ahi + (size_t)(bm + lrow) * K + cbc * 8;
    const __nv_bfloat16* gA1 = Alo + (size_t)(bm + lrow) * K + cbc * 8;
    const __nv_bfloat16* gB0 = Whi + (size_t)(bn + lrow) * K + cbc * 8;
    const __nv_bfloat16* gB1 = Wlo + (size_t)(bn + lrow) * K + cbc * 8;
    const uint32_t dstb = (uint32_t)lrow * AROWB_ + cbc * 16;

    #define ISSUE_STAGE(s, kc) do { \
        uint32_t st_ = sbase + (s) * STG_B + dstb; \
        cpa16(st_,               gA0 + (kc)); cpa16(st_ + 16,               gA0 + (kc) + 8); \
        cpa16(st_ +   MATB_,     gA1 + (kc)); cpa16(st_ +   MATB_ + 16,     gA1 + (kc) + 8); \
        cpa16(st_ + 2*MATB_,     gB0 + (kc)); cpa16(st_ + 2*MATB_ + 16,     gB0 + (kc) + 8); \
        cpa16(st_ + 3*MATB_,     gB1 + (kc)); cpa16(st_ + 3*MATB_ + 16,     gB1 + (kc) + 8); \
    } while (0)

    ISSUE_STAGE(0, 0);  CP_COMMIT();
    ISSUE_STAGE(1, 32); CP_COMMIT();

    float acc[4][4][4];
    #pragma unroll
    for (int mi = 0; mi < 4; mi++)
        #pragma unroll
        for (int nj = 0; nj < 4; nj++)
            #pragma unroll
            for (int r = 0; r < 4; r++) acc[mi][nj][r] = 0.f;

    // ldmatrix per-lane source rows (non-trans for BOTH operands)
    const uint32_t a_row = (uint32_t)(wm*64 + (lane & 15)) * AROWB_;
    const uint32_t a_kh  = (uint32_t)(lane >> 4) * 16;
    const uint32_t b_row = (uint32_t)(wn*32 + ((lane >> 4) << 3) + (lane & 7)) * AROWB_;
    const uint32_t b_kh  = (uint32_t)((lane >> 3) & 1) * 16;

    for (int c = 0; c < nchunk; ++c) {
        CP_WAIT1();
        __syncthreads();

        const uint32_t st = sbase + (c & 1) * STG_B;
        #pragma unroll
        for (int ks = 0; ks < 2; ks++) {
            const uint32_t akb = (uint32_t)ks*32 + a_kh;
            const uint32_t bkb = (uint32_t)ks*32 + b_kh;
            uint32_t bh[4][2], bl[4][2];
            #pragma unroll
            for (int np = 0; np < 2; np++) {
                uint32_t r4[4];
                ldsm4(r4, st + 2*MATB_ + b_row + (uint32_t)np*16*AROWB_ + bkb);
                bh[np*2][0] = r4[0]; bh[np*2][1] = r4[1];
                bh[np*2+1][0] = r4[2]; bh[np*2+1][1] = r4[3];
                ldsm4(r4, st + 3*MATB_ + b_row + (uint32_t)np*16*AROWB_ + bkb);
                bl[np*2][0] = r4[0]; bl[np*2][1] = r4[1];
                bl[np*2+1][0] = r4[2]; bl[np*2+1][1] = r4[3];
            }
            #pragma unroll
            for (int mi = 0; mi < 4; mi++) {
                uint32_t ah[4], al[4];
                ldsm4(ah, st +         a_row + (uint32_t)mi*16*AROWB_ + akb);
                ldsm4(al, st + MATB_ + a_row + (uint32_t)mi*16*AROWB_ + akb);
                // pass-major: consecutive mmas target different accumulators
                #pragma unroll
                for (int nj = 0; nj < 4; nj++) mma16816(acc[mi][nj], ah, bh[nj]);
                #pragma unroll
                for (int nj = 0; nj < 4; nj++) mma16816(acc[mi][nj], ah, bl[nj]);
                #pragma unroll
                for (int nj = 0; nj < 4; nj++) mma16816(acc[mi][nj], al, bh[nj]);
            }
        }
        __syncthreads();   // buffer (c&1) free for reuse
        if (c + 2 < nchunk) { ISSUE_STAGE((c & 1), (c + 2) * 32); }
        CP_COMMIT();       // uniform ledger (empty group near tail)
    }

    // epilogue
    #pragma unroll
    for (int mi = 0; mi < 4; mi++) {
        const int r0 = bm + wm*64 + mi*16 + (lane >> 2);
        #pragma unroll
        for (int nj = 0; nj < 4; nj++) {
            const int cc = bn + wn*32 + nj*8 + (lane & 3)*2;
            float b0 = bias[cc], b1 = bias[cc+1];
            float v00 = acc[mi][nj][0] + b0, v01 = acc[mi][nj][1] + b1;
            float v10 = acc[mi][nj][2] + b0, v11 = acc[mi][nj][3] + b1;
            if (DO_GELU) {
                v00 = gelu_exact(v00); v01 = gelu_exact(v01);
                v10 = gelu_exact(v10); v11 = gelu_exact(v11);
            }
            if (WRITE_SPLIT) {
                __nv_bfloat16 h0,l0,h1,l1;
                fsplit(v00,h0,l0); fsplit(v01,h1,l1);
                *(__nv_bfloat162*)(Chi + (size_t)r0*Nc + cc) = __nv_bfloat162(h0,h1);
                *(__nv_bfloat162*)(Clo + (size_t)r0*Nc + cc) = __nv_bfloat162(l0,l1);
                fsplit(v10,h0,l0); fsplit(v11,h1,l1);
                *(__nv_bfloat162*)(Chi + (size_t)(r0+8)*Nc + cc) = __nv_bfloat162(h0,h1);
                *(__nv_bfloat162*)(Clo + (size_t)(r0+8)*Nc + cc) = __nv_bfloat162(l0,l1);
            } else {
                float2 w0; w0.x = v00; w0.y = v01;
                float2 w1; w1.x = v10; w1.y = v11;
                *(float2*)&C[(size_t)r0     * Nc + cc] = w0;
                *(float2*)&C[(size_t)(r0+8) * Nc + cc] = w1;
            }
        }
    }
    #undef ISSUE_STAGE
}

// ---------------- spatial attention (emits bf16 hi/lo directly) -----------------
__global__ void __launch_bounds__(256) spatial_attn_kernel(
    const float* __restrict__ Q, const float* __restrict__ K,
    const float* __restrict__ V,
    __nv_bfloat16* __restrict__ Ohi, __nv_bfloat16* __restrict__ Olo)
{
    const int bt = blockIdx.x;
    const int h  = blockIdx.y;
    extern __shared__ float sm[];
    float* Ks = sm;                // [256][64]
    float* Vs = sm + PP_*DD_;      // [256][64]

    const int tid = threadIdx.x;
    const size_t base = (size_t)bt * PP_ * EE_ + h * DD_;

    for (int idx = tid; idx < PP_*DD_; idx += 256) {
        int p = idx >> 6, d = idx & 63;
        size_t g = base + (size_t)p * EE_ + d;
        Ks[idx] = K[g];
        Vs[idx] = V[g];
    }
    __syncthreads();

    float qf[DD_];
    const float* qp = Q + base + (size_t)tid * EE_;
    #pragma unroll
    for (int d4 = 0; d4 < DD_/4; d4++) {
        float4 t = *(const float4*)(qp + d4*4);
        qf[d4*4+0]=t.x; qf[d4*4+1]=t.y; qf[d4*4+2]=t.z; qf[d4*4+3]=t.w;
    }

    float m = -1e30f, l = 0.f;
    float acc[DD_];
    #pragma unroll
    for (int d = 0; d < DD_; d++) acc[d] = 0.f;

    for (int j = 0; j < PP_; j++) {
        const float4* kj = (const float4*)(Ks + j*DD_);
        float s = 0.f;
        #pragma unroll
        for (int d4 = 0; d4 < DD_/4; d4++) {
            float4 kv = kj[d4];
            s = fmaf(qf[d4*4+0], kv.x, s);
            s = fmaf(qf[d4*4+1], kv.y, s);
            s = fmaf(qf[d4*4+2], kv.z, s);
            s = fmaf(qf[d4*4+3], kv.w, s);
        }
        s *= SCALE_;
        float mn = fmaxf(m, s);
        float c  = __expf(m - mn);
        float pj = __expf(s - mn);
        l = l * c + pj;
        const float4* vj = (const float4*)(Vs + j*DD_);
        #pragma unroll
        for (int d4 = 0; d4 < DD_/4; d4++) {
            float4 vv = vj[d4];
            acc[d4*4+0] = fmaf(acc[d4*4+0], c, pj*vv.x);
            acc[d4*4+1] = fmaf(acc[d4*4+1], c, pj*vv.y);
            acc[d4*4+2] = fmaf(acc[d4*4+2], c, pj*vv.z);
            acc[d4*4+3] = fmaf(acc[d4*4+3], c, pj*vv.w);
        }
        m = mn;
    }

    float invl = 1.0f / l;
    const size_t ob = base + (size_t)tid * EE_;
    #pragma unroll
    for (int d2 = 0; d2 < DD_/2; d2++) {
        float a0 = acc[d2*2+0]*invl, a1 = acc[d2*2+1]*invl;
        __nv_bfloat16 h0,l0,h1,l1;
        fsplit(a0,h0,l0); fsplit(a1,h1,l1);
        *(__nv_bfloat162*)(Ohi + ob + d2*2) = __nv_bfloat162(h0,h1);
        *(__nv_bfloat162*)(Olo + ob + d2*2) = __nv_bfloat162(l0,l1);
    }
}

// ---------------- temporal attention (emits bf16 hi/lo directly) ----------------
__global__ void __launch_bounds__(192) temporal_attn_kernel(
    const float* __restrict__ Q, const float* __restrict__ K,
    const float* __restrict__ V,
    __nv_bfloat16* __restrict__ Ohi, __nv_bfloat16* __restrict__ Olo)
{
    const int bp = blockIdx.x;
    const int b = bp >> 8;
    const int p = bp & 255;
    extern __shared__ float sm[];
    float* Ks = sm;               // [16][768]
    float* Vs = sm + TT_*EE_;

    const int tid = threadIdx.x;
    for (int idx = tid; idx < TT_*EE_; idx += 192) {
        int t = idx / EE_;
        int e = idx - t*EE_;
        size_t g = ((size_t)(b*TT_ + t) * PP_ + p) * EE_ + e;
        Ks[idx] = K[g];
        Vs[idx] = V[g];
    }
    __syncthreads();

    const int h  = tid >> 4;      // 0..11
    const int tq = tid & 15;      // 0..15

    const size_t qoff = ((size_t)(b*TT_ + tq) * PP_ + p) * EE_ + h * DD_;
    float qf[DD_];
    #pragma unroll
    for (int d4 = 0; d4 < DD_/4; d4++) {
        float4 t4 = *(const float4*)(Q + qoff + d4*4);
        qf[d4*4+0]=t4.x; qf[d4*4+1]=t4.y; qf[d4*4+2]=t4.z; qf[d4*4+3]=t4.w;
    }

    float sc[TT_];
    float m = -1e30f;
    #pragma unroll
    for (int s_ = 0; s_ < TT_; s_++) {
        const float* kr = Ks + s_*EE_ + h*DD_;
        float s = 0.f;
        #pragma unroll
        for (int d = 0; d < DD_; d++) s = fmaf(qf[d], kr[d], s);
        s *= SCALE_;
        if (s_ > tq) s = -1e30f;    // causal mask
        sc[s_] = s;
        m = fmaxf(m, s);
    }
    float l = 0.f;
    #pragma unroll
    for (int s_ = 0; s_ < TT_; s_++) {
        sc[s_] = __expf(sc[s_] - m);
        l += sc[s_];
    }
    float inv = 1.0f / l;

    float acc[DD_];
    #pragma unroll
    for (int d = 0; d < DD_; d++) acc[d] = 0.f;
    #pragma unroll
    for (int s_ = 0; s_ < TT_; s_++) {
        const float* vr = Vs + s_*EE_ + h*DD_;
        float w = sc[s_];
        #pragma unroll
        for (int d = 0; d < DD_; d++) acc[d] = fmaf(w, vr[d], acc[d]);
    }

    #pragma unroll
    for (int d2 = 0; d2 < DD_/2; d2++) {
        float a0 = acc[d2*2+0]*inv, a1 = acc[d2*2+1]*inv;
        __nv_bfloat16 h0,l0,h1,l1;
        fsplit(a0,h0,l0); fsplit(a1,h1,l1);
        *(__nv_bfloat162*)(Ohi + qoff + d2*2) = __nv_bfloat162(h0,h1);
        *(__nv_bfloat162*)(Olo + qoff + d2*2) = __nv_bfloat162(l0,l1);
    }
}

// ---------------- fused residual add + LayerNorm (+ optional hi/lo emit) --------
template<bool EMIT_SPLIT>
__global__ void __launch_bounds__(256) add_ln_kernel(
    const float* __restrict__ x, const float* __restrict__ r,
    const float* __restrict__ gamma, const float* __restrict__ beta,
    float* __restrict__ out,
    __nv_bfloat16* __restrict__ Ohi, __nv_bfloat16* __restrict__ Olo)
{
    const int row = blockIdx.x;
    const float* xr = x + (size_t)row * EE_;
    const float* rr = r + (size_t)row * EE_;

    float vals[3];
    float s = 0.f, ss = 0.f;
    #pragma unroll
    for (int i = 0; i < 3; i++) {
        int e = threadIdx.x + i*256;
        float v = xr[e] + rr[e];
        vals[i] = v;
        s += v;
        ss = fmaf(v, v, ss);
    }
    #pragma unroll
    for (int o = 16; o > 0; o >>= 1) {
        s  += __shfl_down_sync(0xffffffffu, s,  o);
        ss += __shfl_down_sync(0xffffffffu, ss, o);
    }
    __shared__ float reds[8], redss[8];
    int warp = threadIdx.x >> 5, lane = threadIdx.x & 31;
    if (lane == 0) { reds[warp] = s; redss[warp] = ss; }
    __syncthreads();
    float ts = 0.f, tss = 0.f;
    #pragma unroll
    for (int w = 0; w < 8; w++) { ts += reds[w]; tss += redss[w]; }

    const float invE = 1.0f / (float)EE_;
    float mean = ts * invE;
    float var  = tss * invE - mean * mean;
    float inv  = rsqrtf(var + EPS_);

    float* orow = out + (size_t)row * EE_;
    #pragma unroll
    for (int i = 0; i < 3; i++) {
        int e = threadIdx.x + i*256;
        float o = (vals[i] - mean) * inv * gamma[e] + beta[e];
        orow[e] = o;
        if (EMIT_SPLIT) {
            __nv_bfloat16 h, l;
            fsplit(o, h, l);
            Ohi[(size_t)row*EE_ + e] = h;
            Olo[(size_t)row*EE_ + e] = l;
        }
    }
}

// ---------------- host launcher ----------------
// canonical indices (dict order of setup_inputs)
enum { iX=0, iSQW, iSKW, iSVW, iSOW, iSQB, iSKB, iSVB, iSOB, iSG, iSB,
       iTQW, iTKW, iTVW, iTOW, iTQB, iTKB, iTVB, iTOB, iTG, iTB,
       iW1, iB1, iW2, iB2, iG, iBBb };

extern "C" void kernel_launch(void* const* d_in, const int* in_sizes, int n_in,
                              void* d_out, int out_size)
{
    // Resolve input ordering at runtime:
    //  dict order:      idx2 = sk_w (589824)
    //  signature order: idx2 = sq_b (768)
    static const int map_dict[27] = {0,1,2,3,4,5,6,7,8,9,10,11,12,13,14,15,16,17,18,19,20,21,22,23,24,25,26};
    static const int map_sig [27] = {0,1,3,5,7,2,4,6,8,9,10,11,13,15,17,12,14,16,18,19,20,21,22,23,24,25,26};
    const int* mp = (in_sizes[2] == 768) ? map_sig : map_dict;

    const float* in[27];
    for (int i = 0; i < 27; i++) in[i] = (const float*)d_in[mp[i]];

    float *gx, *gq, *gk, *gv, *gt;
    __nv_bfloat16 *ahi, *alo, *bhi, *blo, *whi, *wlo;
    cudaGetSymbolAddress((void**)&gx,  g_x);
    cudaGetSymbolAddress((void**)&gq,  g_q);
    cudaGetSymbolAddress((void**)&gk,  g_k);
    cudaGetSymbolAddress((void**)&gv,  g_v);
    cudaGetSymbolAddress((void**)&gt,  g_t);
    cudaGetSymbolAddress((void**)&ahi, g_ahi);
    cudaGetSymbolAddress((void**)&alo, g_alo);
    cudaGetSymbolAddress((void**)&bhi, g_bhi);
    cudaGetSymbolAddress((void**)&blo, g_blo);
    cudaGetSymbolAddress((void**)&whi, g_whi);
    cudaGetSymbolAddress((void**)&wlo, g_wlo);

    const int SPAT_SMEM = 2 * PP_ * DD_ * (int)sizeof(float);   // 128 KB
    const int TEMP_SMEM = 2 * TT_ * EE_ * (int)sizeof(float);   //  96 KB
    cudaFuncSetAttribute(spatial_attn_kernel,  cudaFuncAttributeMaxDynamicSharedMemorySize, SPAT_SMEM);
    cudaFuncSetAttribute(temporal_attn_kernel, cudaFuncAttributeMaxDynamicSharedMemorySize, TEMP_SMEM);
    cudaFuncSetAttribute((const void*)mma_gemm_kernel<false,false>, cudaFuncAttributeMaxDynamicSharedMemorySize, GSMEM_TOTAL_);
    cudaFuncSetAttribute((const void*)mma_gemm_kernel<true,true>,   cudaFuncAttributeMaxDynamicSharedMemorySize, GSMEM_TOTAL_);

    float* out = (float*)d_out;

    // ---- weight prep: 3 launches (8 batched E x E, then w1, w2) ----
    const size_t offW_F1 = 8*(size_t)WSZ_E;                 // w1
    const size_t offW_F2 = 8*(size_t)WSZ_E + (size_t)WSZ_F; // w2
    wprep8_kernel<<<dim3(EE_/32, EE_/32, 8), 256>>>(
        in[iSQW], in[iSKW], in[iSVW], in[iSOW],
        in[iTQW], in[iTKW], in[iTVW], in[iTOW], whi, wlo);
    wprep_kernel<<<dim3(DFF_/32, EE_/32), 256>>>(in[iW1], whi+offW_F1, wlo+offW_F1, EE_, DFF_);
    wprep_kernel<<<dim3(EE_/32, DFF_/32), 256>>>(in[iW2], whi+offW_F2, wlo+offW_F2, DFF_, EE_);

    const dim3 gemmBlk(256);
    const dim3 gE(EE_/128,  NN_/128);   // (6,128)
    const dim3 gF(DFF_/128, NN_/128);   // (24,128)
    const int NE = NN_*EE_;
    const size_t oE = (size_t)WSZ_E;

    #define GEMM_F(grid, A0, A1, W0, W1, B, Cout, Kd, Nd) \
        mma_gemm_kernel<false,false><<<grid, gemmBlk, GSMEM_TOTAL_>>>( \
            A0, A1, W0, W1, B, Cout, (\
            __nv_bfloat16*)nullptr, (__nv_bfloat16*)nullptr, Kd, Nd)

    // ---- spatial block ----
    split_kernel<<<(NE+255)/256, 256>>>(in[iX], ahi, alo, NE);
    GEMM_F(gE, ahi, alo, whi,      wlo,      in[iSQB], gq, EE_, EE_);   // launch #4 -> ncu -s 5 hits next
    GEMM_F(gE, ahi, alo, whi+oE,   wlo+oE,   in[iSKB], gk, EE_, EE_);
    GEMM_F(gE, ahi, alo, whi+2*oE, wlo+2*oE, in[iSVB], gv, EE_, EE_);
    spatial_attn_kernel<<<dim3(BB_*TT_, HH_), 256, SPAT_SMEM>>>(gq, gk, gv, ahi, alo);
    GEMM_F(gE, ahi, alo, whi+3*oE, wlo+3*oE, in[iSOB], gq, EE_, EE_);
    add_ln_kernel<true><<<NN_, 256>>>(in[iX], gq, in[iSG], in[iSB], gx, ahi, alo);

    // ---- temporal block ----
    GEMM_F(gE, ahi, alo, whi+4*oE, wlo+4*oE, in[iTQB], gq, EE_, EE_);
    GEMM_F(gE, ahi, alo, whi+5*oE, wlo+5*oE, in[iTKB], gk, EE_, EE_);
    GEMM_F(gE, ahi, alo, whi+6*oE, wlo+6*oE, in[iTVB], gv, EE_, EE_);
    temporal_attn_kernel<<<BB_*PP_, 192, TEMP_SMEM>>>(gq, gk, gv, ahi, alo);
    GEMM_F(gE, ahi, alo, whi+7*oE, wlo+7*oE, in[iTOB], gq, EE_, EE_);
    add_ln_kernel<true><<<NN_, 256>>>(gx, gq, in[iTG], in[iTB], gt, ahi, alo);

    // ---- FFN ----
    mma_gemm_kernel<true,true><<<gF, gemmBlk, GSMEM_TOTAL_>>>(
        ahi, alo, whi+offW_F1, wlo+offW_F1, in[iB1],
        (float*)nullptr, bhi, blo, EE_, DFF_);
    GEMM_F(gE, bhi, blo, whi+offW_F2, wlo+offW_F2, in[iB2], gq, DFF_, EE_);
    add_ln_kernel<false><<<NN_, 256>>>(gt, gq, in[iG], in[iBBb], out,
        (__nv_bfloat16*)nullptr, (__nv_bfloat16*)nullptr);

    #undef GEMM_F
}